// round 14
// baseline (speedup 1.0000x reference)
#include <cuda_runtime.h>
#include <cuda_bf16.h>
#include <cuda_fp16.h>
#include <cstdint>
#include <math.h>

#define BB 2
#define SS 1024
#define DD 768
#define HH 12
#define DK 64
#define FF 3072
#define LL 4
#define VV 32000
#define MTOK (BB*SS)   /* 2048 */

// ---------------- scratch ----------------------------------------------------
__device__ float g_h  [MTOK*DD];
__device__ float g_p  [3*MTOK*DD];        // split-K partials
__device__ __half g_t16 [VV*DD];          // tok_emb fp16 (LM head B)
__device__ __half g_e16h[MTOK*DD], g_e16l[MTOK*DD];   // LN outputs fp16 hi/lo
__device__ __half g_w16q[LL*DD*DD], g_w16k[LL*DD*DD], g_w16v[LL*DD*DD];
__device__ __half g_w16o[LL*DD*DD];
__device__ __half g_w16f1[LL*FF*DD], g_w16f2[LL*DD*FF];
__device__ __half g_q16h[MTOK*DD], g_q16l[MTOK*DD];
__device__ __half g_k16 [MTOK*DD], g_v16 [MTOK*DD];
__device__ __half g_a16h[MTOK*DD], g_a16l[MTOK*DD];   // attention ctx fp16 hi/lo
__device__ __half g_f16h[MTOK*FF], g_f16l[MTOK*FF];   // relu(ffn) fp16 hi/lo

// ---------------- helpers ----------------------------------------------------
__device__ __forceinline__ uint32_t smem_u32(const void* p) {
    uint32_t a;
    asm("{ .reg .u64 t; cvta.to.shared.u64 t, %1; cvt.u32.u64 %0, t; }" : "=r"(a) : "l"(p));
    return a;
}
__device__ __forceinline__ void cpasync16(uint32_t saddr, const void* gaddr) {
    asm volatile("cp.async.cg.shared.global [%0], [%1], 16;" :: "r"(saddr), "l"(gaddr));
}
#define CP_COMMIT() asm volatile("cp.async.commit_group;" ::: "memory")
#define CP_WAIT(N)  asm volatile("cp.async.wait_group %0;" :: "n"(N) : "memory")

__device__ __forceinline__ void ldsm4(uint32_t* r, uint32_t addr) {
    asm volatile("ldmatrix.sync.aligned.m8n8.x4.shared.b16 {%0,%1,%2,%3}, [%4];"
        : "=r"(r[0]), "=r"(r[1]), "=r"(r[2]), "=r"(r[3]) : "r"(addr));
}
__device__ __forceinline__ void ldsm4t(uint32_t* r, uint32_t addr) {
    asm volatile("ldmatrix.sync.aligned.m8n8.x4.trans.shared.b16 {%0,%1,%2,%3}, [%4];"
        : "=r"(r[0]), "=r"(r[1]), "=r"(r[2]), "=r"(r[3]) : "r"(addr));
}
__device__ __forceinline__ void mma16816h(float* c, const uint32_t* a, const uint32_t* b) {
    asm volatile(
        "mma.sync.aligned.m16n8k16.row.col.f32.f16.f16.f32 "
        "{%0,%1,%2,%3}, {%4,%5,%6,%7}, {%8,%9}, {%0,%1,%2,%3};"
        : "+f"(c[0]), "+f"(c[1]), "+f"(c[2]), "+f"(c[3])
        : "r"(a[0]), "r"(a[1]), "r"(a[2]), "r"(a[3]), "r"(b[0]), "r"(b[1]));
}
__device__ __forceinline__ void split1h(float v, __half& h, __half& l) {
    h = __float2half(v);
    l = __float2half(v - __half2float(h));
}
__device__ __forceinline__ uint32_t packh(float v0, float v1) {
    __half2 p(__float2half(v0), __float2half(v1));
    return *(uint32_t*)&p;
}

// ---------------- embed ------------------------------------------------------
__global__ void embedcvt_kernel(const long long* __restrict__ x64,
                                const float* __restrict__ tok,
                                const float* __restrict__ pos) {
    __shared__ int is64s;
    if (threadIdx.x == 0) {
        int ok = 1;
        for (int i = 0; i < 16; i++) { long long t = x64[i]; if (t < 0 || t >= VV) ok = 0; }
        is64s = ok;
    }
    __syncthreads();
    int idx = blockIdx.x * blockDim.x + threadIdx.x;
    if (idx < MTOK * DD) {
        int d = idx % DD, t = idx / DD, s = t % SS;
        int tokid = is64s ? (int)x64[t] : ((const int*)x64)[t];
        g_h[idx] = tok[tokid * DD + d] + pos[s * DD + d];
    }
}

// ---------------- warp-per-row layernorms -> fp16 hi/lo ----------------------
__global__ __launch_bounds__(256)
void ln16_kernel(const float* __restrict__ in, const float* __restrict__ g,
                 const float* __restrict__ b,
                 __half* __restrict__ ohi, __half* __restrict__ olo) {
    const int wid = threadIdx.x >> 5, lane = threadIdx.x & 31;
    const int row = blockIdx.x * 8 + wid;
    const float4* xr = (const float4*)(in + (size_t)row * DD);
    float4 v[6];
    float s1 = 0.f, s2 = 0.f;
#pragma unroll
    for (int i = 0; i < 6; i++) {
        v[i] = xr[lane + 32 * i];
        s1 += v[i].x + v[i].y + v[i].z + v[i].w;
        s2 += v[i].x*v[i].x + v[i].y*v[i].y + v[i].z*v[i].z + v[i].w*v[i].w;
    }
#pragma unroll
    for (int o = 16; o > 0; o >>= 1) {
        s1 += __shfl_xor_sync(0xffffffffu, s1, o);
        s2 += __shfl_xor_sync(0xffffffffu, s2, o);
    }
    float mu = s1 * (1.0f / DD);
    float inv = rsqrtf(s2 * (1.0f / DD) - mu * mu + 1e-5f);
    const float4* gg = (const float4*)g;
    const float4* bb = (const float4*)b;
#pragma unroll
    for (int i = 0; i < 6; i++) {
        int e4 = lane + 32 * i;
        float4 gv = gg[e4], bv = bb[e4];
        float o0 = (v[i].x - mu) * inv * gv.x + bv.x;
        float o1 = (v[i].y - mu) * inv * gv.y + bv.y;
        float o2 = (v[i].z - mu) * inv * gv.z + bv.z;
        float o3 = (v[i].w - mu) * inv * gv.w + bv.w;
        __half h0,l0,h1,l1,h2,l2,h3,l3;
        split1h(o0,h0,l0); split1h(o1,h1,l1); split1h(o2,h2,l2); split1h(o3,h3,l3);
        size_t base = (size_t)row * DD + e4 * 4;
        *(__half2*)&ohi[base]     = __half2(h0, h1);
        *(__half2*)&ohi[base + 2] = __half2(h2, h3);
        *(__half2*)&olo[base]     = __half2(l0, l1);
        *(__half2*)&olo[base + 2] = __half2(l2, l3);
    }
}

__global__ __launch_bounds__(256)
void ln_res16_kernel(float* __restrict__ h, const float* __restrict__ p,
                     const float* __restrict__ g, const float* __restrict__ b,
                     __half* __restrict__ ohi, __half* __restrict__ olo) {
    const int wid = threadIdx.x >> 5, lane = threadIdx.x & 31;
    const int row = blockIdx.x * 8 + wid;
    float4* hr = (float4*)(h + (size_t)row * DD);
    const float4* p0 = (const float4*)(p + (size_t)row * DD);
    const float4* p1 = (const float4*)(p + (size_t)MTOK * DD + (size_t)row * DD);
    const float4* p2 = (const float4*)(p + 2 * (size_t)MTOK * DD + (size_t)row * DD);
    float4 v[6];
    float s1 = 0.f, s2 = 0.f;
#pragma unroll
    for (int i = 0; i < 6; i++) {
        int e4 = lane + 32 * i;
        float4 hv = hr[e4], a0 = p0[e4], a1 = p1[e4], a2 = p2[e4];
        hv.x += a0.x + a1.x + a2.x;
        hv.y += a0.y + a1.y + a2.y;
        hv.z += a0.z + a1.z + a2.z;
        hv.w += a0.w + a1.w + a2.w;
        hr[e4] = hv;
        v[i] = hv;
        s1 += hv.x + hv.y + hv.z + hv.w;
        s2 += hv.x*hv.x + hv.y*hv.y + hv.z*hv.z + hv.w*hv.w;
    }
#pragma unroll
    for (int o = 16; o > 0; o >>= 1) {
        s1 += __shfl_xor_sync(0xffffffffu, s1, o);
        s2 += __shfl_xor_sync(0xffffffffu, s2, o);
    }
    float mu = s1 * (1.0f / DD);
    float inv = rsqrtf(s2 * (1.0f / DD) - mu * mu + 1e-5f);
    const float4* gg = (const float4*)g;
    const float4* bb = (const float4*)b;
#pragma unroll
    for (int i = 0; i < 6; i++) {
        int e4 = lane + 32 * i;
        float4 gv = gg[e4], bv = bb[e4];
        float o0 = (v[i].x - mu) * inv * gv.x + bv.x;
        float o1 = (v[i].y - mu) * inv * gv.y + bv.y;
        float o2 = (v[i].z - mu) * inv * gv.z + bv.z;
        float o3 = (v[i].w - mu) * inv * gv.w + bv.w;
        __half h0,l0,h1,l1,h2,l2,h3,l3;
        split1h(o0,h0,l0); split1h(o1,h1,l1); split1h(o2,h2,l2); split1h(o3,h3,l3);
        size_t base = (size_t)row * DD + e4 * 4;
        *(__half2*)&ohi[base]     = __half2(h0, h1);
        *(__half2*)&ohi[base + 2] = __half2(h2, h3);
        *(__half2*)&olo[base]     = __half2(l0, l1);
        *(__half2*)&olo[base + 2] = __half2(l2, l3);
    }
}

// ---------------- fp32 -> fp16 weight converts -------------------------------
__global__ void cvt16_kernel(const float4* __restrict__ x, __half2* __restrict__ o, int n4) {
    int i = blockIdx.x * blockDim.x + threadIdx.x;
    if (i < n4) {
        float4 v = x[i];
        o[2*i]   = __floats2half2_rn(v.x, v.y);
        o[2*i+1] = __floats2half2_rn(v.z, v.w);
    }
}

__global__ void cvtw6_kernel(const float4* s0, __half2* o0, int n0,
                             const float4* s1, __half2* o1, int n1,
                             const float4* s2, __half2* o2, int n2,
                             const float4* s3, __half2* o3, int n3,
                             const float4* s4, __half2* o4, int n4_,
                             const float4* s5, __half2* o5, int n5) {
    const float4* s; __half2* o; int n;
    switch (blockIdx.y) {
        case 0: s = s0; o = o0; n = n0; break;
        case 1: s = s1; o = o1; n = n1; break;
        case 2: s = s2; o = o2; n = n2; break;
        case 3: s = s3; o = o3; n = n3; break;
        case 4: s = s4; o = o4; n = n4_; break;
        default: s = s5; o = o5; n = n5; break;
    }
    int i = blockIdx.x * blockDim.x + threadIdx.x;
    if (i < n) {
        float4 v = s[i];
        o[2*i]   = __floats2half2_rn(v.x, v.y);
        o[2*i+1] = __floats2half2_rn(v.z, v.w);
    }
}

// ---------------- fp16 2-pass GEMM core (4 warps, 64x64 warp tiles) ----------
#define RB     48
#define TILE16 (128*RB)                  /* 6144 B  */
#define NSTG   4
#define LSTG   (3*TILE16)                /* 18432 */
#define GSMEM_H (NSTG*LSTG)              /* 73728 */

// EPI: 0 f32 out (+opt bias), 5 fp16split+bias+scale (opt lo), 6 relu+bias+fp16split
template<int EPI>
__device__ __forceinline__ void hgemm_core(
        const __half* Ah, const __half* Al, const __half* Bh,
        const float* bias, float sc,
        float* C, __half* Chi, __half* Clo,
        int m0, int n0, int N, int K, int ldk, uint32_t sb) {
    const int tid = threadIdx.x;
    const int wid = tid >> 5, lane = tid & 31;
    const int wm = (wid >> 1) * 64;
    const int wn = (wid & 1) * 64;

    float Cf[4][8][4];
#pragma unroll
    for (int i = 0; i < 4; i++)
#pragma unroll
        for (int j = 0; j < 8; j++)
#pragma unroll
            for (int x = 0; x < 4; x++) Cf[i][j][x] = 0.f;

    const int NS = K >> 4;
    const int a_row = (lane & 15);
    const int a_cs = ((lane >> 4) * 8) * 2;
    const int b_row = (lane & 7) + ((lane >> 4) & 1) * 8;
    const int b_cs = (((lane >> 3) & 1) * 8) * 2;

#define LOAD_H(S_)                                                              \
    do {                                                                        \
        const int k0_ = (S_) << 4;                                              \
        uint32_t tb = sb + ((S_) & (NSTG - 1)) * LSTG + tid * RB;               \
        const __half* pa = Ah + (size_t)(m0 + tid) * ldk + k0_;                 \
        const __half* pl = Al + (size_t)(m0 + tid) * ldk + k0_;                 \
        const __half* pb = Bh + (size_t)(n0 + tid) * ldk + k0_;                 \
        cpasync16(tb, pa);                  cpasync16(tb + 16, pa + 8);         \
        cpasync16(tb + TILE16, pl);         cpasync16(tb + TILE16 + 16, pl + 8);\
        cpasync16(tb + 2 * TILE16, pb);     cpasync16(tb + 2*TILE16 + 16, pb + 8);\
    } while (0)

#pragma unroll
    for (int s = 0; s < NSTG - 1; s++) { LOAD_H(s); CP_COMMIT(); }

    for (int s = 0; s < NS; s++) {
        CP_WAIT(NSTG - 2);
        __syncthreads();

        const uint32_t st = sb + (s & (NSTG - 1)) * LSTG;
        uint32_t Af[4][4], Bf[4][4];
#pragma unroll
        for (int mf = 0; mf < 4; mf++)
            ldsm4(Af[mf], st + (wm + mf * 16 + a_row) * RB + a_cs);
#pragma unroll
        for (int p = 0; p < 4; p++)
            ldsm4(Bf[p], st + 2 * TILE16 + (wn + p * 16 + b_row) * RB + b_cs);
#pragma unroll
        for (int mf = 0; mf < 4; mf++)
#pragma unroll
            for (int nf = 0; nf < 8; nf++)
                mma16816h(Cf[mf][nf], Af[mf], &Bf[nf >> 1][(nf & 1) * 2]);
#pragma unroll
        for (int mf = 0; mf < 4; mf++)
            ldsm4(Af[mf], st + TILE16 + (wm + mf * 16 + a_row) * RB + a_cs);
#pragma unroll
        for (int mf = 0; mf < 4; mf++)
#pragma unroll
            for (int nf = 0; nf < 8; nf++)
                mma16816h(Cf[mf][nf], Af[mf], &Bf[nf >> 1][(nf & 1) * 2]);

        if (s + NSTG - 1 < NS) LOAD_H(s + NSTG - 1);
        CP_COMMIT();
    }
#undef LOAD_H

    const int g = lane >> 2, t2 = (lane & 3) * 2;
#pragma unroll
    for (int mf = 0; mf < 4; mf++) {
#pragma unroll
        for (int nf = 0; nf < 8; nf++) {
            int n = n0 + wn + nf * 8 + t2;
#pragma unroll
            for (int hrow = 0; hrow < 2; hrow++) {
                int m = m0 + wm + mf * 16 + g + hrow * 8;
                float v0 = Cf[mf][nf][hrow * 2 + 0];
                float v1 = Cf[mf][nf][hrow * 2 + 1];
                if (EPI == 0) {
                    if (bias) { v0 += bias[n]; v1 += bias[n + 1]; }
                    *(float2*)&C[(size_t)m * N + n] = make_float2(v0, v1);
                } else if (EPI == 5) {
                    v0 = (v0 + bias[n]) * sc;
                    v1 = (v1 + bias[n + 1]) * sc;
                    __half h0, l0, h1, l1;
                    split1h(v0, h0, l0); split1h(v1, h1, l1);
                    *(__half2*)&Chi[(size_t)m * N + n] = __half2(h0, h1);
                    if (Clo)
                        *(__half2*)&Clo[(size_t)m * N + n] = __half2(l0, l1);
                } else {
                    v0 = fmaxf(v0 + bias[n], 0.f);
                    v1 = fmaxf(v1 + bias[n + 1], 0.f);
                    __half h0, l0, h1, l1;
                    split1h(v0, h0, l0); split1h(v1, h1, l1);
                    *(__half2*)&Chi[(size_t)m * N + n] = __half2(h0, h1);
                    *(__half2*)&Clo[(size_t)m * N + n] = __half2(l0, l1);
                }
            }
        }
    }
}

// ---------------- fp16 1-pass LM head GEMM (4 warps, 64x64) ------------------
#define L1STG   (2*TILE16)               /* 12288 */
#define GSMEM_L1 (NSTG*L1STG)            /* 49152 */

__global__ __launch_bounds__(128, 2)
void lm_gemm(const __half* __restrict__ Ah, const __half* __restrict__ Bh,
             float* __restrict__ C, int N, int K) {
    extern __shared__ char smem_raw[];
    const uint32_t sb = smem_u32(smem_raw);
    const int tid = threadIdx.x;
    const int wid = tid >> 5, lane = tid & 31;
    const int m0 = blockIdx.y * 128, n0 = blockIdx.x * 128;
    const int wm = (wid >> 1) * 64;
    const int wn = (wid & 1) * 64;

    float Cf[4][8][4];
#pragma unroll
    for (int i = 0; i < 4; i++)
#pragma unroll
        for (int j = 0; j < 8; j++)
#pragma unroll
            for (int x = 0; x < 4; x++) Cf[i][j][x] = 0.f;

    const int NS = K >> 4;
    const int a_row = (lane & 15);
    const int a_cs = ((lane >> 4) * 8) * 2;
    const int b_row = (lane & 7) + ((lane >> 4) & 1) * 8;
    const int b_cs = (((lane >> 3) & 1) * 8) * 2;

#define LOAD_L1(S_)                                                             \
    do {                                                                        \
        const int k0_ = (S_) << 4;                                              \
        uint32_t tb = sb + ((S_) & (NSTG - 1)) * L1STG + tid * RB;              \
        const __half* pa = Ah + (size_t)(m0 + tid) * K + k0_;                   \
        const __half* pb = Bh + (size_t)(n0 + tid) * K + k0_;                   \
        cpasync16(tb, pa);              cpasync16(tb + 16, pa + 8);             \
        cpasync16(tb + TILE16, pb);     cpasync16(tb + TILE16 + 16, pb + 8);    \
    } while (0)

#pragma unroll
    for (int s = 0; s < NSTG - 1; s++) { LOAD_L1(s); CP_COMMIT(); }

    for (int s = 0; s < NS; s++) {
        CP_WAIT(NSTG - 2);
        __syncthreads();

        const uint32_t st = sb + (s & (NSTG - 1)) * L1STG;
        uint32_t Af[4][4], Bf[4][4];
#pragma unroll
        for (int mf = 0; mf < 4; mf++)
            ldsm4(Af[mf], st + (wm + mf * 16 + a_row) * RB + a_cs);
#pragma unroll
        for (int p = 0; p < 4; p++)
            ldsm4(Bf[p], st + TILE16 + (wn + p * 16 + b_row) * RB + b_cs);
#pragma unroll
        for (int mf = 0; mf < 4; mf++)
#pragma unroll
            for (int nf = 0; nf < 8; nf++)
                mma16816h(Cf[mf][nf], Af[mf], &Bf[nf >> 1][(nf & 1) * 2]);

        if (s + NSTG - 1 < NS) LOAD_L1(s + NSTG - 1);
        CP_COMMIT();
    }
#undef LOAD_L1

    const int g = lane >> 2, t2 = (lane & 3) * 2;
#pragma unroll
    for (int mf = 0; mf < 4; mf++) {
#pragma unroll
        for (int nf = 0; nf < 8; nf++) {
            int n = n0 + wn + nf * 8 + t2;
#pragma unroll
            for (int hrow = 0; hrow < 2; hrow++) {
                int m = m0 + wm + mf * 16 + g + hrow * 8;
                *(float2*)&C[(size_t)m * N + n] =
                    make_float2(Cf[mf][nf][hrow * 2], Cf[mf][nf][hrow * 2 + 1]);
            }
        }
    }
}

// W1: relu + fp16 split out
__global__ __launch_bounds__(128, 2)
void ffn1_gemm(const __half* __restrict__ Ah, const __half* __restrict__ Al,
               const __half* __restrict__ Bh, const float* __restrict__ bias,
               __half* __restrict__ Chi, __half* __restrict__ Clo, int N, int K) {
    extern __shared__ char smem_raw[];
    hgemm_core<6>(Ah, Al, Bh, bias, 1.0f, nullptr, Chi, Clo,
                  blockIdx.y * 128, blockIdx.x * 128, N, K, K, smem_u32(smem_raw));
}

// split-K partial GEMM (O-proj, W2)
__global__ __launch_bounds__(128, 2)
void hgemm_pk(const __half* __restrict__ Ah, const __half* __restrict__ Al,
              const __half* __restrict__ Bh, const float* __restrict__ bias,
              float* __restrict__ P, int N, int Kfull, int Ks) {
    extern __shared__ char smem_raw[];
    const int z = blockIdx.z;
    const int k0 = z * Ks;
    hgemm_core<0>(Ah + k0, Al + k0, Bh + k0,
                  z == 0 ? bias : nullptr, 1.0f,
                  P + (size_t)z * MTOK * N, nullptr, nullptr,
                  blockIdx.y * 128, blockIdx.x * 128, N, Ks, Kfull, smem_u32(smem_raw));
}

__global__ __launch_bounds__(128, 2)
void qkv16_gemm(const __half* __restrict__ Ah, const __half* __restrict__ Al,
                const __half* __restrict__ wq, const __half* __restrict__ wk,
                const __half* __restrict__ wv,
                const float* __restrict__ bq, const float* __restrict__ bk,
                const float* __restrict__ bv,
                __half* __restrict__ qh, __half* __restrict__ ql,
                __half* __restrict__ k16, __half* __restrict__ v16) {
    extern __shared__ char smem_raw[];
    const int which = blockIdx.x / 6, nb = blockIdx.x % 6;
    const __half* B = (which == 0) ? wq : (which == 1) ? wk : wv;
    const float* bias = (which == 0) ? bq : (which == 1) ? bk : bv;
    __half* Ch = (which == 0) ? qh : (which == 1) ? k16 : v16;
    __half* Cl = (which == 0) ? ql : nullptr;
    float sc = (which == 0) ? 0.125f : 1.0f;
    hgemm_core<5>(Ah, Al, B, bias, sc, nullptr, Ch, Cl,
                  blockIdx.y * 128, nb * 128, DD, DD, DD, smem_u32(smem_raw));
}

// ---------------- fp16 2-pass MMA flash attention ----------------------------
#define AST 144
#define ATILE (64*AST)
#define ATT_SMEM16 (2*ATILE + 2*2*ATILE)   /* 55296 */

__device__ __forceinline__ void att_load4(uint32_t dst, const void* src,
                                          size_t grow0, int hcol, int tid) {
    int r = tid >> 1, c0 = (tid & 1) * 4;
    const char* p = (const char*)src + ((grow0 + r) * DD + hcol + c0 * 8) * 2;
    uint32_t d = dst + r * AST + c0 * 16;
#pragma unroll
    for (int i = 0; i < 4; i++) cpasync16(d + i * 16, p + i * 16);
}

__global__ __launch_bounds__(128)
void flash_attn(const __half* __restrict__ qh, const __half* __restrict__ ql,
                const __half* __restrict__ k16, const __half* __restrict__ v16,
                __half* __restrict__ chi, __half* __restrict__ clo) {
    const int qt = gridDim.x - 1 - blockIdx.x;
    const int hd = blockIdx.y, b = blockIdx.z;
    extern __shared__ char smc[];
    const uint32_t sb = smem_u32(smc);
    const uint32_t Qh_s = sb, Ql_s = sb + ATILE;
    const uint32_t KV = sb + 2 * ATILE;

    const int tid = threadIdx.x, wid = tid >> 5, lane = tid & 31;
    const size_t qrow0 = (size_t)(b * SS + qt * 64);
    const int hcol = hd * DK;

    att_load4(Qh_s, qh, qrow0, hcol, tid);
    att_load4(Ql_s, ql, qrow0, hcol, tid);
    {
        size_t kr = (size_t)(b * SS);
        att_load4(KV,         k16, kr, hcol, tid);
        att_load4(KV + ATILE, v16, kr, hcol, tid);
    }
    CP_COMMIT();

    float O[8][4];
    float mrow[2] = { -1e30f, -1e30f };
    float lrow[2] = { 0.f, 0.f };
#pragma unroll
    for (int nt = 0; nt < 8; nt++)
#pragma unroll
        for (int x = 0; x < 4; x++) O[nt][x] = 0.f;

    const int g = lane >> 2, t2q = (lane & 3) * 2;
    const int a_row = wid * 16 + (lane & 15);
    const uint32_t a_cs = ((lane >> 4) << 3) * 2;
    const int b_row = (lane & 7) + (((lane >> 4) & 1) << 3);
    const uint32_t b_cs = (((lane >> 3) & 1) << 3) * 2;
    const int v_row = (lane & 15);
    const uint32_t v_cs = ((lane >> 4) << 3) * 2;

    for (int jt = 0; jt <= qt; jt++) {
        if (jt < qt) {
            size_t kr = (size_t)(b * SS + (jt + 1) * 64);
            uint32_t nb = KV + ((jt + 1) & 1) * (2 * ATILE);
            att_load4(nb,         k16, kr, hcol, tid);
            att_load4(nb + ATILE, v16, kr, hcol, tid);
            CP_COMMIT();
            CP_WAIT(1);
        } else {
            CP_WAIT(0);
        }
        __syncthreads();

        const uint32_t Kh_s = KV + (jt & 1) * (2 * ATILE);
        const uint32_t Vh_s = Kh_s + ATILE;

        float S[8][4];
#pragma unroll
        for (int nt = 0; nt < 8; nt++)
#pragma unroll
            for (int x = 0; x < 4; x++) S[nt][x] = 0.f;

#pragma unroll
        for (int ks = 0; ks < 4; ks++) {
            uint32_t Qhf[4], Qlf[4];
            ldsm4(Qhf, Qh_s + a_row * AST + ks * 32 + a_cs);
            ldsm4(Qlf, Ql_s + a_row * AST + ks * 32 + a_cs);
#pragma unroll
            for (int p = 0; p < 4; p++) {
                uint32_t Kf[4];
                ldsm4(Kf, Kh_s + (p * 16 + b_row) * AST + ks * 32 + b_cs);
#pragma unroll
                for (int q = 0; q < 2; q++) {
                    mma16816h(S[p * 2 + q], Qhf, &Kf[q * 2]);
                    mma16816h(S[p * 2 + q], Qlf, &Kf[q * 2]);
                }
            }
        }

        const bool diag = (jt == qt);
#pragma unroll
        for (int half = 0; half < 2; half++) {
            const int rloc = wid * 16 + g + half * 8;
            float mt = -1e30f;
#pragma unroll
            for (int nt = 0; nt < 8; nt++) {
                float s0 = S[nt][half * 2], s1 = S[nt][half * 2 + 1];
                if (diag) {
                    if (nt * 8 + t2q > rloc)     s0 = -1e30f;
                    if (nt * 8 + t2q + 1 > rloc) s1 = -1e30f;
                }
                S[nt][half * 2] = s0; S[nt][half * 2 + 1] = s1;
                mt = fmaxf(mt, fmaxf(s0, s1));
            }
            mt = fmaxf(mt, __shfl_xor_sync(0xffffffffu, mt, 1));
            mt = fmaxf(mt, __shfl_xor_sync(0xffffffffu, mt, 2));
            float mn = fmaxf(mrow[half], mt);
            float f = __expf(mrow[half] - mn);
            mrow[half] = mn;
            float rs = 0.f;
#pragma unroll
            for (int nt = 0; nt < 8; nt++) {
                float e0 = __expf(S[nt][half * 2] - mn);
                float e1 = __expf(S[nt][half * 2 + 1] - mn);
                S[nt][half * 2] = e0; S[nt][half * 2 + 1] = e1;
                rs += e0 + e1;
            }
            rs += __shfl_xor_sync(0xffffffffu, rs, 1);
            rs += __shfl_xor_sync(0xffffffffu, rs, 2);
            lrow[half] = lrow[half] * f + rs;
#pragma unroll
            for (int nt = 0; nt < 8; nt++) {
                O[nt][half * 2] *= f; O[nt][half * 2 + 1] *= f;
            }
        }

#pragma unroll
        for (int ks = 0; ks < 4; ks++) {
            uint32_t Ph[4], Pl[4];
#pragma unroll
            for (int q4 = 0; q4 < 4; q4++) {
                int tile = 2 * ks + (q4 >> 1);
                int o = (q4 & 1) * 2;
                float v0 = S[tile][o], v1 = S[tile][o + 1];
                __half h0 = __float2half(v0), h1 = __float2half(v1);
                __half2 hh(h0, h1);
                Ph[q4] = *(uint32_t*)&hh;
                Pl[q4] = packh(v0 - __half2float(h0), v1 - __half2float(h1));
            }
#pragma unroll
            for (int nt = 0; nt < 4; nt++) {
                uint32_t Vf[4];
                ldsm4t(Vf, Vh_s + (ks * 16 + v_row) * AST + nt * 32 + v_cs);
#pragma unroll
                for (int q = 0; q < 2; q++) {
                    mma16816h(O[nt * 2 + q], Ph, &Vf[q * 2]);
                    mma16816h(O[nt * 2 + q], Pl, &Vf[q * 2]);
                }
            }
        }
        __syncthreads();
    }

    float inv[2] = { 1.0f / lrow[0], 1.0f / lrow[1] };
#pragma unroll
    for (int nt = 0; nt < 8; nt++) {
#pragma unroll
        for (int half = 0; half < 2; half++) {
            size_t row = qrow0 + wid * 16 + g + half * 8;
            int col = hcol + nt * 8 + t2q;
            float v0 = O[nt][half * 2] * inv[half];
            float v1 = O[nt][half * 2 + 1] * inv[half];
            __half h0, l0, h1, l1;
            split1h(v0, h0, l0); split1h(v1, h1, l1);
            *(__half2*)&chi[row * DD + col] = __half2(h0, h1);
            *(__half2*)&clo[row * DD + col] = __half2(l0, l1);
        }
    }
}

// ---------------- driver -----------------------------------------------------
extern "C" void kernel_launch(void* const* d_in, const int* in_sizes, int n_in,
                              void* d_out, int out_size) {
    (void)in_sizes; (void)n_in; (void)out_size;
    const float* tok  = (const float*)d_in[1];
    const float* pos  = (const float*)d_in[2];
    const float* bq   = (const float*)d_in[4];
    const float* bk   = (const float*)d_in[6];
    const float* bv   = (const float*)d_in[8];
    const float* bo   = (const float*)d_in[10];
    const float* b1   = (const float*)d_in[12];
    const float* b2   = (const float*)d_in[14];
    const float* ln1g = (const float*)d_in[15];
    const float* ln1b = (const float*)d_in[16];
    const float* ln2g = (const float*)d_in[17];
    const float* ln2b = (const float*)d_in[18];
    const float* lnfg = (const float*)d_in[19];
    const float* lnfb = (const float*)d_in[20];
    float* out = (float*)d_out;

    float *h, *pp;
    cudaGetSymbolAddress((void**)&h,  g_h);
    cudaGetSymbolAddress((void**)&pp, g_p);

    __half *t16, *e16h, *e16l, *w16q, *w16k, *w16v, *w16o, *w16f1, *w16f2;
    __half *q16h, *q16l, *k16, *v16, *a16h, *a16l, *f16h, *f16l;
    cudaGetSymbolAddress((void**)&t16,   g_t16);
    cudaGetSymbolAddress((void**)&e16h,  g_e16h);
    cudaGetSymbolAddress((void**)&e16l,  g_e16l);
    cudaGetSymbolAddress((void**)&w16q,  g_w16q);
    cudaGetSymbolAddress((void**)&w16k,  g_w16k);
    cudaGetSymbolAddress((void**)&w16v,  g_w16v);
    cudaGetSymbolAddress((void**)&w16o,  g_w16o);
    cudaGetSymbolAddress((void**)&w16f1, g_w16f1);
    cudaGetSymbolAddress((void**)&w16f2, g_w16f2);
    cudaGetSymbolAddress((void**)&q16h,  g_q16h);
    cudaGetSymbolAddress((void**)&q16l,  g_q16l);
    cudaGetSymbolAddress((void**)&k16,   g_k16);
    cudaGetSymbolAddress((void**)&v16,   g_v16);
    cudaGetSymbolAddress((void**)&a16h,  g_a16h);
    cudaGetSymbolAddress((void**)&a16l,  g_a16l);
    cudaGetSymbolAddress((void**)&f16h,  g_f16h);
    cudaGetSymbolAddress((void**)&f16l,  g_f16l);

    cudaFuncSetAttribute(qkv16_gemm, cudaFuncAttributeMaxDynamicSharedMemorySize, GSMEM_H);
    cudaFuncSetAttribute(ffn1_gemm,  cudaFuncAttributeMaxDynamicSharedMemorySize, GSMEM_H);
    cudaFuncSetAttribute(hgemm_pk,   cudaFuncAttributeMaxDynamicSharedMemorySize, GSMEM_H);
    cudaFuncSetAttribute(lm_gemm,    cudaFuncAttributeMaxDynamicSharedMemorySize, GSMEM_L1);
    cudaFuncSetAttribute(flash_attn, cudaFuncAttributeMaxDynamicSharedMemorySize, ATT_SMEM16);

    // launch 0: embed
    embedcvt_kernel<<<(MTOK * DD + 255) / 256, 256>>>((const long long*)d_in[0], tok, pos);
    // launch 1: all six layer weight tensors -> fp16
    {
        const int nD4 = LL * DD * DD / 4;
        const int nF4 = LL * FF * DD / 4;
        dim3 gw((nF4 + 255) / 256, 6);
        cvtw6_kernel<<<gw, 256>>>(
            (const float4*)d_in[3],  (__half2*)w16q,  nD4,
            (const float4*)d_in[5],  (__half2*)w16k,  nD4,
            (const float4*)d_in[7],  (__half2*)w16v,  nD4,
            (const float4*)d_in[9],  (__half2*)w16o,  nD4,
            (const float4*)d_in[11], (__half2*)w16f1, nF4,
            (const float4*)d_in[13], (__half2*)w16f2, nF4);
    }

    dim3 gQKV(18, MTOK / 128);           // (18, 16)
    dim3 gPK(DD / 128, MTOK / 128, 3);   // (6, 16, 3)
    dim3 gF(FF / 128, MTOK / 128);       // (24, 16)
    dim3 gV(VV / 128, MTOK / 128);       // (250, 16)
    dim3 gA(SS / 64, HH, BB);            // (16, 12, 2)
    const int gLN = MTOK / 8;

    for (int l = 0; l < LL; l++) {
        const size_t wD = (size_t)l * DD * DD;
        if (l == 0)
            ln16_kernel<<<gLN, 256>>>(h, ln1g, ln1b, e16h, e16l);          // launch 2
        else
            ln_res16_kernel<<<gLN, 256>>>(h, pp, ln1g + l * DD, ln1b + l * DD, e16h, e16l);
        qkv16_gemm<<<gQKV, 128, GSMEM_H>>>(e16h, e16l,                     // launch 3 (l=0) — profiled
                                           w16q + wD, w16k + wD, w16v + wD,
                                           bq + l * DD, bk + l * DD, bv + l * DD,
                                           q16h, q16l, k16, v16);
        flash_attn<<<gA, 128, ATT_SMEM16>>>(q16h, q16l, k16, v16, a16h, a16l);
        hgemm_pk<<<gPK, 128, GSMEM_H>>>(a16h, a16l, w16o + wD, bo + l * DD,
                                        pp, DD, DD, DD / 3);
        ln_res16_kernel<<<gLN, 256>>>(h, pp, ln2g + l * DD, ln2b + l * DD, e16h, e16l);
        ffn1_gemm<<<gF, 128, GSMEM_H>>>(e16h, e16l, w16f1 + (size_t)l * FF * DD,
                                        b1 + l * FF, f16h, f16l, FF, DD);
        hgemm_pk<<<gPK, 128, GSMEM_H>>>(f16h, f16l, w16f2 + (size_t)l * DD * FF,
                                        b2 + l * DD, pp, DD, FF, FF / 3);
    }

    // LM head (1-pass fp16)
    {
        int n4 = VV * DD / 4;
        cvt16_kernel<<<(n4 + 255) / 256, 256>>>((const float4*)tok, (__half2*)t16, n4);
    }
    ln_res16_kernel<<<gLN, 256>>>(h, pp, lnfg, lnfb, e16h, e16l);
    lm_gemm<<<gV, 128, GSMEM_L1>>>(e16h, t16, out, VV, DD);
}

// round 16
// speedup vs baseline: 1.1089x; 1.1089x over previous
#include <cuda_runtime.h>
#include <cuda_bf16.h>
#include <cuda_fp16.h>
#include <cstdint>
#include <math.h>

#define BB 2
#define SS 1024
#define DD 768
#define HH 12
#define DK 64
#define FF 3072
#define LL 4
#define VV 32000
#define MTOK (BB*SS)   /* 2048 */

// ---------------- scratch ----------------------------------------------------
__device__ float g_h  [MTOK*DD];
__device__ float g_p  [3*MTOK*DD];        // split-K partials
__device__ __half g_t16 [VV*DD];          // tok_emb fp16 (LM head B)
__device__ __half g_e16h[MTOK*DD], g_e16l[MTOK*DD];   // LN outputs fp16 hi/lo
__device__ __half g_w16q[LL*DD*DD], g_w16k[LL*DD*DD], g_w16v[LL*DD*DD];
__device__ __half g_w16o[LL*DD*DD];
__device__ __half g_w16f1[LL*FF*DD], g_w16f2[LL*DD*FF];
__device__ __half g_q16 [MTOK*DD];
__device__ __half g_k16 [MTOK*DD], g_v16 [MTOK*DD];
__device__ __half g_a16h[MTOK*DD], g_a16l[MTOK*DD];   // attention ctx fp16 hi/lo
__device__ __half g_f16h[MTOK*FF], g_f16l[MTOK*FF];   // relu(ffn) fp16 hi/lo

// ---------------- helpers ----------------------------------------------------
__device__ __forceinline__ uint32_t smem_u32(const void* p) {
    uint32_t a;
    asm("{ .reg .u64 t; cvta.to.shared.u64 t, %1; cvt.u32.u64 %0, t; }" : "=r"(a) : "l"(p));
    return a;
}
__device__ __forceinline__ void cpasync16(uint32_t saddr, const void* gaddr) {
    asm volatile("cp.async.cg.shared.global [%0], [%1], 16;" :: "r"(saddr), "l"(gaddr));
}
#define CP_COMMIT() asm volatile("cp.async.commit_group;" ::: "memory")
#define CP_WAIT(N)  asm volatile("cp.async.wait_group %0;" :: "n"(N) : "memory")

__device__ __forceinline__ void ldsm4(uint32_t* r, uint32_t addr) {
    asm volatile("ldmatrix.sync.aligned.m8n8.x4.shared.b16 {%0,%1,%2,%3}, [%4];"
        : "=r"(r[0]), "=r"(r[1]), "=r"(r[2]), "=r"(r[3]) : "r"(addr));
}
__device__ __forceinline__ void ldsm4t(uint32_t* r, uint32_t addr) {
    asm volatile("ldmatrix.sync.aligned.m8n8.x4.trans.shared.b16 {%0,%1,%2,%3}, [%4];"
        : "=r"(r[0]), "=r"(r[1]), "=r"(r[2]), "=r"(r[3]) : "r"(addr));
}
__device__ __forceinline__ void mma16816h(float* c, const uint32_t* a, const uint32_t* b) {
    asm volatile(
        "mma.sync.aligned.m16n8k16.row.col.f32.f16.f16.f32 "
        "{%0,%1,%2,%3}, {%4,%5,%6,%7}, {%8,%9}, {%0,%1,%2,%3};"
        : "+f"(c[0]), "+f"(c[1]), "+f"(c[2]), "+f"(c[3])
        : "r"(a[0]), "r"(a[1]), "r"(a[2]), "r"(a[3]), "r"(b[0]), "r"(b[1]));
}
__device__ __forceinline__ void split1h(float v, __half& h, __half& l) {
    h = __float2half(v);
    l = __float2half(v - __half2float(h));
}
__device__ __forceinline__ uint32_t packh(float v0, float v1) {
    __half2 p(__float2half(v0), __float2half(v1));
    return *(uint32_t*)&p;
}

// ---------------- embed ------------------------------------------------------
__global__ void embedcvt_kernel(const long long* __restrict__ x64,
                                const float* __restrict__ tok,
                                const float* __restrict__ pos) {
    __shared__ int is64s;
    if (threadIdx.x == 0) {
        int ok = 1;
        for (int i = 0; i < 16; i++) { long long t = x64[i]; if (t < 0 || t >= VV) ok = 0; }
        is64s = ok;
    }
    __syncthreads();
    int idx = blockIdx.x * blockDim.x + threadIdx.x;
    if (idx < MTOK * DD) {
        int d = idx % DD, t = idx / DD, s = t % SS;
        int tokid = is64s ? (int)x64[t] : ((const int*)x64)[t];
        g_h[idx] = tok[tokid * DD + d] + pos[s * DD + d];
    }
}

// ---------------- warp-per-row layernorms -> fp16 hi/lo ----------------------
__global__ __launch_bounds__(256)
void ln16_kernel(const float* __restrict__ in, const float* __restrict__ g,
                 const float* __restrict__ b,
                 __half* __restrict__ ohi, __half* __restrict__ olo) {
    const int wid = threadIdx.x >> 5, lane = threadIdx.x & 31;
    const int row = blockIdx.x * 8 + wid;
    const float4* xr = (const float4*)(in + (size_t)row * DD);
    float4 v[6];
    float s1 = 0.f, s2 = 0.f;
#pragma unroll
    for (int i = 0; i < 6; i++) {
        v[i] = xr[lane + 32 * i];
        s1 += v[i].x + v[i].y + v[i].z + v[i].w;
        s2 += v[i].x*v[i].x + v[i].y*v[i].y + v[i].z*v[i].z + v[i].w*v[i].w;
    }
#pragma unroll
    for (int o = 16; o > 0; o >>= 1) {
        s1 += __shfl_xor_sync(0xffffffffu, s1, o);
        s2 += __shfl_xor_sync(0xffffffffu, s2, o);
    }
    float mu = s1 * (1.0f / DD);
    float inv = rsqrtf(s2 * (1.0f / DD) - mu * mu + 1e-5f);
    const float4* gg = (const float4*)g;
    const float4* bb = (const float4*)b;
#pragma unroll
    for (int i = 0; i < 6; i++) {
        int e4 = lane + 32 * i;
        float4 gv = gg[e4], bv = bb[e4];
        float o0 = (v[i].x - mu) * inv * gv.x + bv.x;
        float o1 = (v[i].y - mu) * inv * gv.y + bv.y;
        float o2 = (v[i].z - mu) * inv * gv.z + bv.z;
        float o3 = (v[i].w - mu) * inv * gv.w + bv.w;
        __half h0,l0,h1,l1,h2,l2,h3,l3;
        split1h(o0,h0,l0); split1h(o1,h1,l1); split1h(o2,h2,l2); split1h(o3,h3,l3);
        size_t base = (size_t)row * DD + e4 * 4;
        *(__half2*)&ohi[base]     = __half2(h0, h1);
        *(__half2*)&ohi[base + 2] = __half2(h2, h3);
        *(__half2*)&olo[base]     = __half2(l0, l1);
        *(__half2*)&olo[base + 2] = __half2(l2, l3);
    }
}

__global__ __launch_bounds__(256)
void ln_res16_kernel(float* __restrict__ h, const float* __restrict__ p,
                     const float* __restrict__ g, const float* __restrict__ b,
                     __half* __restrict__ ohi, __half* __restrict__ olo) {
    const int wid = threadIdx.x >> 5, lane = threadIdx.x & 31;
    const int row = blockIdx.x * 8 + wid;
    float4* hr = (float4*)(h + (size_t)row * DD);
    const float4* p0 = (const float4*)(p + (size_t)row * DD);
    const float4* p1 = (const float4*)(p + (size_t)MTOK * DD + (size_t)row * DD);
    const float4* p2 = (const float4*)(p + 2 * (size_t)MTOK * DD + (size_t)row * DD);
    float4 v[6];
    float s1 = 0.f, s2 = 0.f;
#pragma unroll
    for (int i = 0; i < 6; i++) {
        int e4 = lane + 32 * i;
        float4 hv = hr[e4], a0 = p0[e4], a1 = p1[e4], a2 = p2[e4];
        hv.x += a0.x + a1.x + a2.x;
        hv.y += a0.y + a1.y + a2.y;
        hv.z += a0.z + a1.z + a2.z;
        hv.w += a0.w + a1.w + a2.w;
        hr[e4] = hv;
        v[i] = hv;
        s1 += hv.x + hv.y + hv.z + hv.w;
        s2 += hv.x*hv.x + hv.y*hv.y + hv.z*hv.z + hv.w*hv.w;
    }
#pragma unroll
    for (int o = 16; o > 0; o >>= 1) {
        s1 += __shfl_xor_sync(0xffffffffu, s1, o);
        s2 += __shfl_xor_sync(0xffffffffu, s2, o);
    }
    float mu = s1 * (1.0f / DD);
    float inv = rsqrtf(s2 * (1.0f / DD) - mu * mu + 1e-5f);
    const float4* gg = (const float4*)g;
    const float4* bb = (const float4*)b;
#pragma unroll
    for (int i = 0; i < 6; i++) {
        int e4 = lane + 32 * i;
        float4 gv = gg[e4], bv = bb[e4];
        float o0 = (v[i].x - mu) * inv * gv.x + bv.x;
        float o1 = (v[i].y - mu) * inv * gv.y + bv.y;
        float o2 = (v[i].z - mu) * inv * gv.z + bv.z;
        float o3 = (v[i].w - mu) * inv * gv.w + bv.w;
        __half h0,l0,h1,l1,h2,l2,h3,l3;
        split1h(o0,h0,l0); split1h(o1,h1,l1); split1h(o2,h2,l2); split1h(o3,h3,l3);
        size_t base = (size_t)row * DD + e4 * 4;
        *(__half2*)&ohi[base]     = __half2(h0, h1);
        *(__half2*)&ohi[base + 2] = __half2(h2, h3);
        *(__half2*)&olo[base]     = __half2(l0, l1);
        *(__half2*)&olo[base + 2] = __half2(l2, l3);
    }
}

// ---------------- fp32 -> fp16 weight converts -------------------------------
__global__ void cvt16_kernel(const float4* __restrict__ x, __half2* __restrict__ o, int n4) {
    int i = blockIdx.x * blockDim.x + threadIdx.x;
    if (i < n4) {
        float4 v = x[i];
        o[2*i]   = __floats2half2_rn(v.x, v.y);
        o[2*i+1] = __floats2half2_rn(v.z, v.w);
    }
}

__global__ void cvtw6_kernel(const float4* s0, __half2* o0, int n0,
                             const float4* s1, __half2* o1, int n1,
                             const float4* s2, __half2* o2, int n2,
                             const float4* s3, __half2* o3, int n3,
                             const float4* s4, __half2* o4, int n4_,
                             const float4* s5, __half2* o5, int n5) {
    const float4* s; __half2* o; int n;
    switch (blockIdx.y) {
        case 0: s = s0; o = o0; n = n0; break;
        case 1: s = s1; o = o1; n = n1; break;
        case 2: s = s2; o = o2; n = n2; break;
        case 3: s = s3; o = o3; n = n3; break;
        case 4: s = s4; o = o4; n = n4_; break;
        default: s = s5; o = o5; n = n5; break;
    }
    int i = blockIdx.x * blockDim.x + threadIdx.x;
    if (i < n) {
        float4 v = s[i];
        o[2*i]   = __floats2half2_rn(v.x, v.y);
        o[2*i+1] = __floats2half2_rn(v.z, v.w);
    }
}

// ---------------- fp16 2-pass GEMM core (R13 config: 8 warps, 64x32) ---------
#define RB     48
#define TILE16 (128*RB)                  /* 6144 B  */
#define NSTG   4
#define LSTG   (3*TILE16)                /* 18432 */
#define GSMEM_H (NSTG*LSTG)              /* 73728 */

// EPI: 0 f32 out (+opt bias), 5 fp16split+bias+scale (opt lo), 6 relu+bias+fp16split
template<int EPI>
__device__ __forceinline__ void hgemm_core(
        const __half* Ah, const __half* Al, const __half* Bh,
        const float* bias, float sc,
        float* C, __half* Chi, __half* Clo,
        int m0, int n0, int N, int K, int ldk, uint32_t sb) {
    const int tid = threadIdx.x;
    const int wid = tid >> 5, lane = tid & 31;
    const int wm = (wid >> 2) * 64;
    const int wn = (wid & 3) * 32;

    float Cf[4][4][4];
#pragma unroll
    for (int i = 0; i < 4; i++)
#pragma unroll
        for (int j = 0; j < 4; j++)
#pragma unroll
            for (int x = 0; x < 4; x++) Cf[i][j][x] = 0.f;

    const int NS = K >> 4;
    const int a_row = (lane & 15);
    const int a_cs = ((lane >> 4) * 8) * 2;
    const int b_row = (lane & 7) + ((lane >> 4) & 1) * 8;
    const int b_cs = (((lane >> 3) & 1) * 8) * 2;
    const int lr = tid >> 1;
    const int lc = tid & 1;

#define LOAD_H(S_)                                                              \
    do {                                                                        \
        const int k0_ = (S_) << 4;                                              \
        uint32_t tb = sb + ((S_) & (NSTG - 1)) * LSTG + lr * RB + lc * 16;      \
        const int ac_ = k0_ + lc * 8;                                           \
        cpasync16(tb,              Ah + (size_t)(m0 + lr) * ldk + ac_);         \
        cpasync16(tb + TILE16,     Al + (size_t)(m0 + lr) * ldk + ac_);         \
        cpasync16(tb + 2 * TILE16, Bh + (size_t)(n0 + lr) * ldk + ac_);         \
    } while (0)

#pragma unroll
    for (int s = 0; s < NSTG - 1; s++) { LOAD_H(s); CP_COMMIT(); }

    for (int s = 0; s < NS; s++) {
        CP_WAIT(NSTG - 2);
        __syncthreads();

        const uint32_t st = sb + (s & (NSTG - 1)) * LSTG;
        uint32_t Af[4][4], Bf[2][4];
#pragma unroll
        for (int mf = 0; mf < 4; mf++)
            ldsm4(Af[mf], st + (wm + mf * 16 + a_row) * RB + a_cs);
#pragma unroll
        for (int p = 0; p < 2; p++)
            ldsm4(Bf[p], st + 2 * TILE16 + (wn + p * 16 + b_row) * RB + b_cs);
#pragma unroll
        for (int mf = 0; mf < 4; mf++)
#pragma unroll
            for (int nf = 0; nf < 4; nf++)
                mma16816h(Cf[mf][nf], Af[mf], &Bf[nf >> 1][(nf & 1) * 2]);
#pragma unroll
        for (int mf = 0; mf < 4; mf++)
            ldsm4(Af[mf], st + TILE16 + (wm + mf * 16 + a_row) * RB + a_cs);
#pragma unroll
        for (int mf = 0; mf < 4; mf++)
#pragma unroll
            for (int nf = 0; nf < 4; nf++)
                mma16816h(Cf[mf][nf], Af[mf], &Bf[nf >> 1][(nf & 1) * 2]);

        if (s + NSTG - 1 < NS) LOAD_H(s + NSTG - 1);
        CP_COMMIT();
    }
#undef LOAD_H

    const int g = lane >> 2, t2 = (lane & 3) * 2;
#pragma unroll
    for (int mf = 0; mf < 4; mf++) {
#pragma unroll
        for (int nf = 0; nf < 4; nf++) {
            int n = n0 + wn + nf * 8 + t2;
#pragma unroll
            for (int hrow = 0; hrow < 2; hrow++) {
                int m = m0 + wm + mf * 16 + g + hrow * 8;
                float v0 = Cf[mf][nf][hrow * 2 + 0];
                float v1 = Cf[mf][nf][hrow * 2 + 1];
                if (EPI == 0) {
                    if (bias) { v0 += bias[n]; v1 += bias[n + 1]; }
                    *(float2*)&C[(size_t)m * N + n] = make_float2(v0, v1);
                } else if (EPI == 5) {
                    v0 = (v0 + bias[n]) * sc;
                    v1 = (v1 + bias[n + 1]) * sc;
                    __half h0, l0, h1, l1;
                    split1h(v0, h0, l0); split1h(v1, h1, l1);
                    *(__half2*)&Chi[(size_t)m * N + n] = __half2(h0, h1);
                    if (Clo)
                        *(__half2*)&Clo[(size_t)m * N + n] = __half2(l0, l1);
                } else {
                    v0 = fmaxf(v0 + bias[n], 0.f);
                    v1 = fmaxf(v1 + bias[n + 1], 0.f);
                    __half h0, l0, h1, l1;
                    split1h(v0, h0, l0); split1h(v1, h1, l1);
                    *(__half2*)&Chi[(size_t)m * N + n] = __half2(h0, h1);
                    *(__half2*)&Clo[(size_t)m * N + n] = __half2(l0, l1);
                }
            }
        }
    }
}

// ---------------- fp16 1-pass LM head GEMM (R13 config) ----------------------
#define L1STG   (2*TILE16)               /* 12288 */
#define GSMEM_L1 (NSTG*L1STG)            /* 49152 */

__global__ __launch_bounds__(256, 2)
void lm_gemm(const __half* __restrict__ Ah, const __half* __restrict__ Bh,
             float* __restrict__ C, int N, int K) {
    extern __shared__ char smem_raw[];
    const uint32_t sb = smem_u32(smem_raw);
    const int tid = threadIdx.x;
    const int wid = tid >> 5, lane = tid & 31;
    const int m0 = blockIdx.y * 128, n0 = blockIdx.x * 128;
    const int wm = (wid >> 2) * 64;
    const int wn = (wid & 3) * 32;

    float Cf[4][4][4];
#pragma unroll
    for (int i = 0; i < 4; i++)
#pragma unroll
        for (int j = 0; j < 4; j++)
#pragma unroll
            for (int x = 0; x < 4; x++) Cf[i][j][x] = 0.f;

    const int NS = K >> 4;
    const int a_row = (lane & 15);
    const int a_cs = ((lane >> 4) * 8) * 2;
    const int b_row = (lane & 7) + ((lane >> 4) & 1) * 8;
    const int b_cs = (((lane >> 3) & 1) * 8) * 2;
    const int lr = tid >> 1;
    const int lc = tid & 1;

#define LOAD_L1(S_)                                                             \
    do {                                                                        \
        const int k0_ = (S_) << 4;                                              \
        uint32_t tb = sb + ((S_) & (NSTG - 1)) * L1STG + lr * RB + lc * 16;     \
        const int ac_ = k0_ + lc * 8;                                           \
        cpasync16(tb,          Ah + (size_t)(m0 + lr) * K + ac_);               \
        cpasync16(tb + TILE16, Bh + (size_t)(n0 + lr) * K + ac_);               \
    } while (0)

#pragma unroll
    for (int s = 0; s < NSTG - 1; s++) { LOAD_L1(s); CP_COMMIT(); }

    for (int s = 0; s < NS; s++) {
        CP_WAIT(NSTG - 2);
        __syncthreads();

        const uint32_t st = sb + (s & (NSTG - 1)) * L1STG;
        uint32_t Af[4][4], Bf[2][4];
#pragma unroll
        for (int mf = 0; mf < 4; mf++)
            ldsm4(Af[mf], st + (wm + mf * 16 + a_row) * RB + a_cs);
#pragma unroll
        for (int p = 0; p < 2; p++)
            ldsm4(Bf[p], st + TILE16 + (wn + p * 16 + b_row) * RB + b_cs);
#pragma unroll
        for (int mf = 0; mf < 4; mf++)
#pragma unroll
            for (int nf = 0; nf < 4; nf++)
                mma16816h(Cf[mf][nf], Af[mf], &Bf[nf >> 1][(nf & 1) * 2]);

        if (s + NSTG - 1 < NS) LOAD_L1(s + NSTG - 1);
        CP_COMMIT();
    }
#undef LOAD_L1

    const int g = lane >> 2, t2 = (lane & 3) * 2;
#pragma unroll
    for (int mf = 0; mf < 4; mf++) {
#pragma unroll
        for (int nf = 0; nf < 4; nf++) {
            int n = n0 + wn + nf * 8 + t2;
#pragma unroll
            for (int hrow = 0; hrow < 2; hrow++) {
                int m = m0 + wm + mf * 16 + g + hrow * 8;
                *(float2*)&C[(size_t)m * N + n] =
                    make_float2(Cf[mf][nf][hrow * 2], Cf[mf][nf][hrow * 2 + 1]);
            }
        }
    }
}

// W1: relu + fp16 split out
__global__ __launch_bounds__(256, 2)
void ffn1_gemm(const __half* __restrict__ Ah, const __half* __restrict__ Al,
               const __half* __restrict__ Bh, const float* __restrict__ bias,
               __half* __restrict__ Chi, __half* __restrict__ Clo, int N, int K) {
    extern __shared__ char smem_raw[];
    hgemm_core<6>(Ah, Al, Bh, bias, 1.0f, nullptr, Chi, Clo,
                  blockIdx.y * 128, blockIdx.x * 128, N, K, K, smem_u32(smem_raw));
}

// split-K partial GEMM (O-proj, W2)
__global__ __launch_bounds__(256, 2)
void hgemm_pk(const __half* __restrict__ Ah, const __half* __restrict__ Al,
              const __half* __restrict__ Bh, const float* __restrict__ bias,
              float* __restrict__ P, int N, int Kfull, int Ks) {
    extern __shared__ char smem_raw[];
    const int z = blockIdx.z;
    const int k0 = z * Ks;
    hgemm_core<0>(Ah + k0, Al + k0, Bh + k0,
                  z == 0 ? bias : nullptr, 1.0f,
                  P + (size_t)z * MTOK * N, nullptr, nullptr,
                  blockIdx.y * 128, blockIdx.x * 128, N, Ks, Kfull, smem_u32(smem_raw));
}

__global__ __launch_bounds__(256, 2)
void qkv16_gemm(const __half* __restrict__ Ah, const __half* __restrict__ Al,
                const __half* __restrict__ wq, const __half* __restrict__ wk,
                const __half* __restrict__ wv,
                const float* __restrict__ bq, const float* __restrict__ bk,
                const float* __restrict__ bv,
                __half* __restrict__ q16, __half* __restrict__ k16,
                __half* __restrict__ v16) {
    extern __shared__ char smem_raw[];
    const int which = blockIdx.x / 6, nb = blockIdx.x % 6;
    const __half* B = (which == 0) ? wq : (which == 1) ? wk : wv;
    const float* bias = (which == 0) ? bq : (which == 1) ? bk : bv;
    __half* Ch = (which == 0) ? q16 : (which == 1) ? k16 : v16;
    float sc = (which == 0) ? 0.125f : 1.0f;
    hgemm_core<5>(Ah, Al, B, bias, sc, nullptr, Ch, nullptr,
                  blockIdx.y * 128, nb * 128, DD, DD, DD, smem_u32(smem_raw));
}

// ---------------- fp16 1-pass-QK MMA flash attention -------------------------
#define AST 144
#define ATILE (64*AST)
#define ATT_SMEM16 (ATILE + 2*2*ATILE)   /* 46080 */

__device__ __forceinline__ void att_load4(uint32_t dst, const void* src,
                                          size_t grow0, int hcol, int tid) {
    int r = tid >> 1, c0 = (tid & 1) * 4;
    const char* p = (const char*)src + ((grow0 + r) * DD + hcol + c0 * 8) * 2;
    uint32_t d = dst + r * AST + c0 * 16;
#pragma unroll
    for (int i = 0; i < 4; i++) cpasync16(d + i * 16, p + i * 16);
}

__global__ __launch_bounds__(128)
void flash_attn(const __half* __restrict__ q16,
                const __half* __restrict__ k16, const __half* __restrict__ v16,
                __half* __restrict__ chi, __half* __restrict__ clo) {
    const int qt = gridDim.x - 1 - blockIdx.x;
    const int hd = blockIdx.y, b = blockIdx.z;
    extern __shared__ char smc[];
    const uint32_t sb = smem_u32(smc);
    const uint32_t Qh_s = sb;
    const uint32_t KV = sb + ATILE;

    const int tid = threadIdx.x, wid = tid >> 5, lane = tid & 31;
    const size_t qrow0 = (size_t)(b * SS + qt * 64);
    const int hcol = hd * DK;

    att_load4(Qh_s, q16, qrow0, hcol, tid);
    {
        size_t kr = (size_t)(b * SS);
        att_load4(KV,         k16, kr, hcol, tid);
        att_load4(KV + ATILE, v16, kr, hcol, tid);
    }
    CP_COMMIT();

    float O[8][4];
    float mrow[2] = { -1e30f, -1e30f };
    float lrow[2] = { 0.f, 0.f };
#pragma unroll
    for (int nt = 0; nt < 8; nt++)
#pragma unroll
        for (int x = 0; x < 4; x++) O[nt][x] = 0.f;

    const int g = lane >> 2, t2q = (lane & 3) * 2;
    const int a_row = wid * 16 + (lane & 15);
    const uint32_t a_cs = ((lane >> 4) << 3) * 2;
    const int b_row = (lane & 7) + (((lane >> 4) & 1) << 3);
    const uint32_t b_cs = (((lane >> 3) & 1) << 3) * 2;
    const int v_row = (lane & 15);
    const uint32_t v_cs = ((lane >> 4) << 3) * 2;

    for (int jt = 0; jt <= qt; jt++) {
        if (jt < qt) {
            size_t kr = (size_t)(b * SS + (jt + 1) * 64);
            uint32_t nb = KV + ((jt + 1) & 1) * (2 * ATILE);
            att_load4(nb,         k16, kr, hcol, tid);
            att_load4(nb + ATILE, v16, kr, hcol, tid);
            CP_COMMIT();
            CP_WAIT(1);
        } else {
            CP_WAIT(0);
        }
        __syncthreads();

        const uint32_t Kh_s = KV + (jt & 1) * (2 * ATILE);
        const uint32_t Vh_s = Kh_s + ATILE;

        float S[8][4];
#pragma unroll
        for (int nt = 0; nt < 8; nt++)
#pragma unroll
            for (int x = 0; x < 4; x++) S[nt][x] = 0.f;

#pragma unroll
        for (int ks = 0; ks < 4; ks++) {
            uint32_t Qf[4];
            ldsm4(Qf, Qh_s + a_row * AST + ks * 32 + a_cs);
#pragma unroll
            for (int p = 0; p < 4; p++) {
                uint32_t Kf[4];
                ldsm4(Kf, Kh_s + (p * 16 + b_row) * AST + ks * 32 + b_cs);
#pragma unroll
                for (int q = 0; q < 2; q++)
                    mma16816h(S[p * 2 + q], Qf, &Kf[q * 2]);
            }
        }

        const bool diag = (jt == qt);
#pragma unroll
        for (int half = 0; half < 2; half++) {
            const int rloc = wid * 16 + g + half * 8;
            float mt = -1e30f;
#pragma unroll
            for (int nt = 0; nt < 8; nt++) {
                float s0 = S[nt][half * 2], s1 = S[nt][half * 2 + 1];
                if (diag) {
                    if (nt * 8 + t2q > rloc)     s0 = -1e30f;
                    if (nt * 8 + t2q + 1 > rloc) s1 = -1e30f;
                }
                S[nt][half * 2] = s0; S[nt][half * 2 + 1] = s1;
                mt = fmaxf(mt, fmaxf(s0, s1));
            }
            mt = fmaxf(mt, __shfl_xor_sync(0xffffffffu, mt, 1));
            mt = fmaxf(mt, __shfl_xor_sync(0xffffffffu, mt, 2));
            float mn = fmaxf(mrow[half], mt);
            float f = __expf(mrow[half] - mn);
            mrow[half] = mn;
            float rs = 0.f;
#pragma unroll
            for (int nt = 0; nt < 8; nt++) {
                float e0 = __expf(S[nt][half * 2] - mn);
                float e1 = __expf(S[nt][half * 2 + 1] - mn);
                S[nt][half * 2] = e0; S[nt][half * 2 + 1] = e1;
                rs += e0 + e1;
            }
            rs += __shfl_xor_sync(0xffffffffu, rs, 1);
            rs += __shfl_xor_sync(0xffffffffu, rs, 2);
            lrow[half] = lrow[half] * f + rs;
#pragma unroll
            for (int nt = 0; nt < 8; nt++) {
                O[nt][half * 2] *= f; O[nt][half * 2 + 1] *= f;
            }
        }

#pragma unroll
        for (int ks = 0; ks < 4; ks++) {
            uint32_t Ph[4], Pl[4];
#pragma unroll
            for (int q4 = 0; q4 < 4; q4++) {
                int tile = 2 * ks + (q4 >> 1);
                int o = (q4 & 1) * 2;
                float v0 = S[tile][o], v1 = S[tile][o + 1];
                __half h0 = __float2half(v0), h1 = __float2half(v1);
                __half2 hh(h0, h1);
                Ph[q4] = *(uint32_t*)&hh;
                Pl[q4] = packh(v0 - __half2float(h0), v1 - __half2float(h1));
            }
#pragma unroll
            for (int nt = 0; nt < 4; nt++) {
                uint32_t Vf[4];
                ldsm4t(Vf, Vh_s + (ks * 16 + v_row) * AST + nt * 32 + v_cs);
#pragma unroll
                for (int q = 0; q < 2; q++) {
                    mma16816h(O[nt * 2 + q], Ph, &Vf[q * 2]);
                    mma16816h(O[nt * 2 + q], Pl, &Vf[q * 2]);
                }
            }
        }
        __syncthreads();
    }

    float inv[2] = { 1.0f / lrow[0], 1.0f / lrow[1] };
#pragma unroll
    for (int nt = 0; nt < 8; nt++) {
#pragma unroll
        for (int half = 0; half < 2; half++) {
            size_t row = qrow0 + wid * 16 + g + half * 8;
            int col = hcol + nt * 8 + t2q;
            float v0 = O[nt][half * 2] * inv[half];
            float v1 = O[nt][half * 2 + 1] * inv[half];
            __half h0, l0, h1, l1;
            split1h(v0, h0, l0); split1h(v1, h1, l1);
            *(__half2*)&chi[row * DD + col] = __half2(h0, h1);
            *(__half2*)&clo[row * DD + col] = __half2(l0, l1);
        }
    }
}

// ---------------- driver -----------------------------------------------------
extern "C" void kernel_launch(void* const* d_in, const int* in_sizes, int n_in,
                              void* d_out, int out_size) {
    (void)in_sizes; (void)n_in; (void)out_size;
    const float* tok  = (const float*)d_in[1];
    const float* pos  = (const float*)d_in[2];
    const float* bq   = (const float*)d_in[4];
    const float* bk   = (const float*)d_in[6];
    const float* bv   = (const float*)d_in[8];
    const float* bo   = (const float*)d_in[10];
    const float* b1   = (const float*)d_in[12];
    const float* b2   = (const float*)d_in[14];
    const float* ln1g = (const float*)d_in[15];
    const float* ln1b = (const float*)d_in[16];
    const float* ln2g = (const float*)d_in[17];
    const float* ln2b = (const float*)d_in[18];
    const float* lnfg = (const float*)d_in[19];
    const float* lnfb = (const float*)d_in[20];
    float* out = (float*)d_out;

    float *h, *pp;
    cudaGetSymbolAddress((void**)&h,  g_h);
    cudaGetSymbolAddress((void**)&pp, g_p);

    __half *t16, *e16h, *e16l, *w16q, *w16k, *w16v, *w16o, *w16f1, *w16f2;
    __half *q16, *k16, *v16, *a16h, *a16l, *f16h, *f16l;
    cudaGetSymbolAddress((void**)&t16,   g_t16);
    cudaGetSymbolAddress((void**)&e16h,  g_e16h);
    cudaGetSymbolAddress((void**)&e16l,  g_e16l);
    cudaGetSymbolAddress((void**)&w16q,  g_w16q);
    cudaGetSymbolAddress((void**)&w16k,  g_w16k);
    cudaGetSymbolAddress((void**)&w16v,  g_w16v);
    cudaGetSymbolAddress((void**)&w16o,  g_w16o);
    cudaGetSymbolAddress((void**)&w16f1, g_w16f1);
    cudaGetSymbolAddress((void**)&w16f2, g_w16f2);
    cudaGetSymbolAddress((void**)&q16,   g_q16);
    cudaGetSymbolAddress((void**)&k16,   g_k16);
    cudaGetSymbolAddress((void**)&v16,   g_v16);
    cudaGetSymbolAddress((void**)&a16h,  g_a16h);
    cudaGetSymbolAddress((void**)&a16l,  g_a16l);
    cudaGetSymbolAddress((void**)&f16h,  g_f16h);
    cudaGetSymbolAddress((void**)&f16l,  g_f16l);

    cudaFuncSetAttribute(qkv16_gemm, cudaFuncAttributeMaxDynamicSharedMemorySize, GSMEM_H);
    cudaFuncSetAttribute(ffn1_gemm,  cudaFuncAttributeMaxDynamicSharedMemorySize, GSMEM_H);
    cudaFuncSetAttribute(hgemm_pk,   cudaFuncAttributeMaxDynamicSharedMemorySize, GSMEM_H);
    cudaFuncSetAttribute(lm_gemm,    cudaFuncAttributeMaxDynamicSharedMemorySize, GSMEM_L1);
    cudaFuncSetAttribute(flash_attn, cudaFuncAttributeMaxDynamicSharedMemorySize, ATT_SMEM16);

    // launch 0: embed
    embedcvt_kernel<<<(MTOK * DD + 255) / 256, 256>>>((const long long*)d_in[0], tok, pos);
    // launch 1: all six layer weight tensors -> fp16
    {
        const int nD4 = LL * DD * DD / 4;
        const int nF4 = LL * FF * DD / 4;
        dim3 gw((nF4 + 255) / 256, 6);
        cvtw6_kernel<<<gw, 256>>>(
            (const float4*)d_in[3],  (__half2*)w16q,  nD4,
            (const float4*)d_in[5],  (__half2*)w16k,  nD4,
            (const float4*)d_in[7],  (__half2*)w16v,  nD4,
            (const float4*)d_in[9],  (__half2*)w16o,  nD4,
            (const float4*)d_in[11], (__half2*)w16f1, nF4,
            (const float4*)d_in[13], (__half2*)w16f2, nF4);
    }

    dim3 gQKV(18, MTOK / 128);           // (18, 16)
    dim3 gPK(DD / 128, MTOK / 128, 3);   // (6, 16, 3)
    dim3 gF(FF / 128, MTOK / 128);       // (24, 16)
    dim3 gV(VV / 128, MTOK / 128);       // (250, 16)
    dim3 gA(SS / 64, HH, BB);            // (16, 12, 2)
    const int gLN = MTOK / 8;

    for (int l = 0; l < LL; l++) {
        const size_t wD = (size_t)l * DD * DD;
        if (l == 0)
            ln16_kernel<<<gLN, 256>>>(h, ln1g, ln1b, e16h, e16l);          // launch 2
        else
            ln_res16_kernel<<<gLN, 256>>>(h, pp, ln1g + l * DD, ln1b + l * DD, e16h, e16l);
        qkv16_gemm<<<gQKV, 256, GSMEM_H>>>(e16h, e16l,                     // launch 3 (l=0) — profiled
                                           w16q + wD, w16k + wD, w16v + wD,
                                           bq + l * DD, bk + l * DD, bv + l * DD,
                                           q16, k16, v16);
        flash_attn<<<gA, 128, ATT_SMEM16>>>(q16, k16, v16, a16h, a16l);
        hgemm_pk<<<gPK, 256, GSMEM_H>>>(a16h, a16l, w16o + wD, bo + l * DD,
                                        pp, DD, DD, DD / 3);
        ln_res16_kernel<<<gLN, 256>>>(h, pp, ln2g + l * DD, ln2b + l * DD, e16h, e16l);
        ffn1_gemm<<<gF, 256, GSMEM_H>>>(e16h, e16l, w16f1 + (size_t)l * FF * DD,
                                        b1 + l * FF, f16h, f16l, FF, DD);
        hgemm_pk<<<gPK, 256, GSMEM_H>>>(f16h, f16l, w16f2 + (size_t)l * DD * FF,
                                        b2 + l * DD, pp, DD, FF, FF / 3);
    }

    // LM head (1-pass fp16)
    {
        int n4 = VV * DD / 4;
        cvt16_kernel<<<(n4 + 255) / 256, 256>>>((const float4*)tok, (__half2*)t16, n4);
    }
    ln_res16_kernel<<<gLN, 256>>>(h, pp, lnfg, lnfb, e16h, e16l);
    lm_gemm<<<gV, 256, GSMEM_L1>>>(e16h, t16, out, VV, DD);
}

// round 17
// speedup vs baseline: 1.2416x; 1.1197x over previous
#include <cuda_runtime.h>
#include <cuda_bf16.h>
#include <cuda_fp16.h>
#include <cstdint>
#include <math.h>

#define BB 2
#define SS 1024
#define DD 768
#define HH 12
#define DK 64
#define FF 3072
#define LL 4
#define VV 32000
#define MTOK (BB*SS)   /* 2048 */

// ---------------- scratch ----------------------------------------------------
__device__ float g_h  [MTOK*DD];
__device__ float g_p  [3*MTOK*DD];        // split-K partials
__device__ __half g_t16 [VV*DD];          // tok_emb fp16 (LM head B)
__device__ __half g_e16h[MTOK*DD], g_e16l[MTOK*DD];   // LN outputs fp16 hi/lo
__device__ __half g_w16q[LL*DD*DD], g_w16k[LL*DD*DD], g_w16v[LL*DD*DD];
__device__ __half g_w16o[LL*DD*DD];
__device__ __half g_w16f1[LL*FF*DD], g_w16f2[LL*DD*FF];
__device__ __half g_q16 [MTOK*DD];
__device__ __half g_k16 [MTOK*DD], g_v16 [MTOK*DD];
__device__ __half g_a16 [MTOK*DD];        // attention ctx fp16 (single plane)
__device__ __half g_f16 [MTOK*FF];        // relu(ffn) fp16 (single plane)

// ---------------- helpers ----------------------------------------------------
__device__ __forceinline__ uint32_t smem_u32(const void* p) {
    uint32_t a;
    asm("{ .reg .u64 t; cvta.to.shared.u64 t, %1; cvt.u32.u64 %0, t; }" : "=r"(a) : "l"(p));
    return a;
}
__device__ __forceinline__ void cpasync16(uint32_t saddr, const void* gaddr) {
    asm volatile("cp.async.cg.shared.global [%0], [%1], 16;" :: "r"(saddr), "l"(gaddr));
}
#define CP_COMMIT() asm volatile("cp.async.commit_group;" ::: "memory")
#define CP_WAIT(N)  asm volatile("cp.async.wait_group %0;" :: "n"(N) : "memory")

__device__ __forceinline__ void ldsm4(uint32_t* r, uint32_t addr) {
    asm volatile("ldmatrix.sync.aligned.m8n8.x4.shared.b16 {%0,%1,%2,%3}, [%4];"
        : "=r"(r[0]), "=r"(r[1]), "=r"(r[2]), "=r"(r[3]) : "r"(addr));
}
__device__ __forceinline__ void ldsm4t(uint32_t* r, uint32_t addr) {
    asm volatile("ldmatrix.sync.aligned.m8n8.x4.trans.shared.b16 {%0,%1,%2,%3}, [%4];"
        : "=r"(r[0]), "=r"(r[1]), "=r"(r[2]), "=r"(r[3]) : "r"(addr));
}
__device__ __forceinline__ void mma16816h(float* c, const uint32_t* a, const uint32_t* b) {
    asm volatile(
        "mma.sync.aligned.m16n8k16.row.col.f32.f16.f16.f32 "
        "{%0,%1,%2,%3}, {%4,%5,%6,%7}, {%8,%9}, {%0,%1,%2,%3};"
        : "+f"(c[0]), "+f"(c[1]), "+f"(c[2]), "+f"(c[3])
        : "r"(a[0]), "r"(a[1]), "r"(a[2]), "r"(a[3]), "r"(b[0]), "r"(b[1]));
}
__device__ __forceinline__ void split1h(float v, __half& h, __half& l) {
    h = __float2half(v);
    l = __float2half(v - __half2float(h));
}

// ---------------- embed ------------------------------------------------------
__global__ void embedcvt_kernel(const long long* __restrict__ x64,
                                const float* __restrict__ tok,
                                const float* __restrict__ pos) {
    __shared__ int is64s;
    if (threadIdx.x == 0) {
        int ok = 1;
        for (int i = 0; i < 16; i++) { long long t = x64[i]; if (t < 0 || t >= VV) ok = 0; }
        is64s = ok;
    }
    __syncthreads();
    int idx = blockIdx.x * blockDim.x + threadIdx.x;
    if (idx < MTOK * DD) {
        int d = idx % DD, t = idx / DD, s = t % SS;
        int tokid = is64s ? (int)x64[t] : ((const int*)x64)[t];
        g_h[idx] = tok[tokid * DD + d] + pos[s * DD + d];
    }
}

// ---------------- warp-per-row layernorms -> fp16 hi/lo ----------------------
__global__ __launch_bounds__(256)
void ln16_kernel(const float* __restrict__ in, const float* __restrict__ g,
                 const float* __restrict__ b,
                 __half* __restrict__ ohi, __half* __restrict__ olo) {
    const int wid = threadIdx.x >> 5, lane = threadIdx.x & 31;
    const int row = blockIdx.x * 8 + wid;
    const float4* xr = (const float4*)(in + (size_t)row * DD);
    float4 v[6];
    float s1 = 0.f, s2 = 0.f;
#pragma unroll
    for (int i = 0; i < 6; i++) {
        v[i] = xr[lane + 32 * i];
        s1 += v[i].x + v[i].y + v[i].z + v[i].w;
        s2 += v[i].x*v[i].x + v[i].y*v[i].y + v[i].z*v[i].z + v[i].w*v[i].w;
    }
#pragma unroll
    for (int o = 16; o > 0; o >>= 1) {
        s1 += __shfl_xor_sync(0xffffffffu, s1, o);
        s2 += __shfl_xor_sync(0xffffffffu, s2, o);
    }
    float mu = s1 * (1.0f / DD);
    float inv = rsqrtf(s2 * (1.0f / DD) - mu * mu + 1e-5f);
    const float4* gg = (const float4*)g;
    const float4* bb = (const float4*)b;
#pragma unroll
    for (int i = 0; i < 6; i++) {
        int e4 = lane + 32 * i;
        float4 gv = gg[e4], bv = bb[e4];
        float o0 = (v[i].x - mu) * inv * gv.x + bv.x;
        float o1 = (v[i].y - mu) * inv * gv.y + bv.y;
        float o2 = (v[i].z - mu) * inv * gv.z + bv.z;
        float o3 = (v[i].w - mu) * inv * gv.w + bv.w;
        __half h0,l0,h1,l1,h2,l2,h3,l3;
        split1h(o0,h0,l0); split1h(o1,h1,l1); split1h(o2,h2,l2); split1h(o3,h3,l3);
        size_t base = (size_t)row * DD + e4 * 4;
        *(__half2*)&ohi[base]     = __half2(h0, h1);
        *(__half2*)&ohi[base + 2] = __half2(h2, h3);
        *(__half2*)&olo[base]     = __half2(l0, l1);
        *(__half2*)&olo[base + 2] = __half2(l2, l3);
    }
}

__global__ __launch_bounds__(256)
void ln_res16_kernel(float* __restrict__ h, const float* __restrict__ p,
                     const float* __restrict__ g, const float* __restrict__ b,
                     __half* __restrict__ ohi, __half* __restrict__ olo) {
    const int wid = threadIdx.x >> 5, lane = threadIdx.x & 31;
    const int row = blockIdx.x * 8 + wid;
    float4* hr = (float4*)(h + (size_t)row * DD);
    const float4* p0 = (const float4*)(p + (size_t)row * DD);
    const float4* p1 = (const float4*)(p + (size_t)MTOK * DD + (size_t)row * DD);
    const float4* p2 = (const float4*)(p + 2 * (size_t)MTOK * DD + (size_t)row * DD);
    float4 v[6];
    float s1 = 0.f, s2 = 0.f;
#pragma unroll
    for (int i = 0; i < 6; i++) {
        int e4 = lane + 32 * i;
        float4 hv = hr[e4], a0 = p0[e4], a1 = p1[e4], a2 = p2[e4];
        hv.x += a0.x + a1.x + a2.x;
        hv.y += a0.y + a1.y + a2.y;
        hv.z += a0.z + a1.z + a2.z;
        hv.w += a0.w + a1.w + a2.w;
        hr[e4] = hv;
        v[i] = hv;
        s1 += hv.x + hv.y + hv.z + hv.w;
        s2 += hv.x*hv.x + hv.y*hv.y + hv.z*hv.z + hv.w*hv.w;
    }
#pragma unroll
    for (int o = 16; o > 0; o >>= 1) {
        s1 += __shfl_xor_sync(0xffffffffu, s1, o);
        s2 += __shfl_xor_sync(0xffffffffu, s2, o);
    }
    float mu = s1 * (1.0f / DD);
    float inv = rsqrtf(s2 * (1.0f / DD) - mu * mu + 1e-5f);
    const float4* gg = (const float4*)g;
    const float4* bb = (const float4*)b;
#pragma unroll
    for (int i = 0; i < 6; i++) {
        int e4 = lane + 32 * i;
        float4 gv = gg[e4], bv = bb[e4];
        float o0 = (v[i].x - mu) * inv * gv.x + bv.x;
        float o1 = (v[i].y - mu) * inv * gv.y + bv.y;
        float o2 = (v[i].z - mu) * inv * gv.z + bv.z;
        float o3 = (v[i].w - mu) * inv * gv.w + bv.w;
        __half h0,l0,h1,l1,h2,l2,h3,l3;
        split1h(o0,h0,l0); split1h(o1,h1,l1); split1h(o2,h2,l2); split1h(o3,h3,l3);
        size_t base = (size_t)row * DD + e4 * 4;
        *(__half2*)&ohi[base]     = __half2(h0, h1);
        *(__half2*)&ohi[base + 2] = __half2(h2, h3);
        *(__half2*)&olo[base]     = __half2(l0, l1);
        *(__half2*)&olo[base + 2] = __half2(l2, l3);
    }
}

// ---------------- fp32 -> fp16 weight converts -------------------------------
__global__ void cvt16_kernel(const float4* __restrict__ x, __half2* __restrict__ o, int n4) {
    int i = blockIdx.x * blockDim.x + threadIdx.x;
    if (i < n4) {
        float4 v = x[i];
        o[2*i]   = __floats2half2_rn(v.x, v.y);
        o[2*i+1] = __floats2half2_rn(v.z, v.w);
    }
}

__global__ void cvtw6_kernel(const float4* s0, __half2* o0, int n0,
                             const float4* s1, __half2* o1, int n1,
                             const float4* s2, __half2* o2, int n2,
                             const float4* s3, __half2* o3, int n3,
                             const float4* s4, __half2* o4, int n4_,
                             const float4* s5, __half2* o5, int n5) {
    const float4* s; __half2* o; int n;
    switch (blockIdx.y) {
        case 0: s = s0; o = o0; n = n0; break;
        case 1: s = s1; o = o1; n = n1; break;
        case 2: s = s2; o = o2; n = n2; break;
        case 3: s = s3; o = o3; n = n3; break;
        case 4: s = s4; o = o4; n = n4_; break;
        default: s = s5; o = o5; n = n5; break;
    }
    int i = blockIdx.x * blockDim.x + threadIdx.x;
    if (i < n) {
        float4 v = s[i];
        o[2*i]   = __floats2half2_rn(v.x, v.y);
        o[2*i+1] = __floats2half2_rn(v.z, v.w);
    }
}

// ---------------- fp16 GEMM core (NP passes; 8 warps, 64x32 tiles) -----------
#define RB     48
#define TILE16 (128*RB)                  /* 6144 B  */
#define NSTG   4
#define GSMEM_H  (NSTG*3*TILE16)         /* 73728 (2-pass) */
#define GSMEM_L1 (NSTG*2*TILE16)         /* 49152 (1-pass) */

// EPI: 0 f32 out (+opt bias), 5 fp16+bias+scale, 6 relu+bias+fp16
template<int EPI, int NP>
__device__ __forceinline__ void hgemm_core(
        const __half* Ah, const __half* Al, const __half* Bh,
        const float* bias, float sc,
        float* C, __half* Ch,
        int m0, int n0, int N, int K, int ldk, uint32_t sb) {
    constexpr int STG = (NP + 1) * TILE16;
    const int tid = threadIdx.x;
    const int wid = tid >> 5, lane = tid & 31;
    const int wm = (wid >> 2) * 64;
    const int wn = (wid & 3) * 32;

    float Cf[4][4][4];
#pragma unroll
    for (int i = 0; i < 4; i++)
#pragma unroll
        for (int j = 0; j < 4; j++)
#pragma unroll
            for (int x = 0; x < 4; x++) Cf[i][j][x] = 0.f;

    const int NS = K >> 4;
    const int a_row = (lane & 15);
    const int a_cs = ((lane >> 4) * 8) * 2;
    const int b_row = (lane & 7) + ((lane >> 4) & 1) * 8;
    const int b_cs = (((lane >> 3) & 1) * 8) * 2;
    const int lr = tid >> 1;
    const int lc = tid & 1;

#define LOAD_H(S_)                                                              \
    do {                                                                        \
        const int k0_ = (S_) << 4;                                              \
        uint32_t tb = sb + ((S_) & (NSTG - 1)) * STG + lr * RB + lc * 16;       \
        const int ac_ = k0_ + lc * 8;                                           \
        cpasync16(tb, Ah + (size_t)(m0 + lr) * ldk + ac_);                      \
        if (NP == 2)                                                            \
            cpasync16(tb + TILE16, Al + (size_t)(m0 + lr) * ldk + ac_);         \
        cpasync16(tb + NP * TILE16, Bh + (size_t)(n0 + lr) * ldk + ac_);        \
    } while (0)

#pragma unroll
    for (int s = 0; s < NSTG - 1; s++) { LOAD_H(s); CP_COMMIT(); }

    for (int s = 0; s < NS; s++) {
        CP_WAIT(NSTG - 2);
        __syncthreads();

        const uint32_t st = sb + (s & (NSTG - 1)) * STG;
        uint32_t Af[4][4], Bf[2][4];
#pragma unroll
        for (int mf = 0; mf < 4; mf++)
            ldsm4(Af[mf], st + (wm + mf * 16 + a_row) * RB + a_cs);
#pragma unroll
        for (int p = 0; p < 2; p++)
            ldsm4(Bf[p], st + NP * TILE16 + (wn + p * 16 + b_row) * RB + b_cs);
#pragma unroll
        for (int mf = 0; mf < 4; mf++)
#pragma unroll
            for (int nf = 0; nf < 4; nf++)
                mma16816h(Cf[mf][nf], Af[mf], &Bf[nf >> 1][(nf & 1) * 2]);
        if (NP == 2) {
#pragma unroll
            for (int mf = 0; mf < 4; mf++)
                ldsm4(Af[mf], st + TILE16 + (wm + mf * 16 + a_row) * RB + a_cs);
#pragma unroll
            for (int mf = 0; mf < 4; mf++)
#pragma unroll
                for (int nf = 0; nf < 4; nf++)
                    mma16816h(Cf[mf][nf], Af[mf], &Bf[nf >> 1][(nf & 1) * 2]);
        }

        if (s + NSTG - 1 < NS) LOAD_H(s + NSTG - 1);
        CP_COMMIT();
    }
#undef LOAD_H

    const int g = lane >> 2, t2 = (lane & 3) * 2;
#pragma unroll
    for (int mf = 0; mf < 4; mf++) {
#pragma unroll
        for (int nf = 0; nf < 4; nf++) {
            int n = n0 + wn + nf * 8 + t2;
#pragma unroll
            for (int hrow = 0; hrow < 2; hrow++) {
                int m = m0 + wm + mf * 16 + g + hrow * 8;
                float v0 = Cf[mf][nf][hrow * 2 + 0];
                float v1 = Cf[mf][nf][hrow * 2 + 1];
                if (EPI == 0) {
                    if (bias) { v0 += bias[n]; v1 += bias[n + 1]; }
                    *(float2*)&C[(size_t)m * N + n] = make_float2(v0, v1);
                } else if (EPI == 5) {
                    v0 = (v0 + bias[n]) * sc;
                    v1 = (v1 + bias[n + 1]) * sc;
                    *(__half2*)&Ch[(size_t)m * N + n] = __floats2half2_rn(v0, v1);
                } else {
                    v0 = fmaxf(v0 + bias[n], 0.f);
                    v1 = fmaxf(v1 + bias[n + 1], 0.f);
                    *(__half2*)&Ch[(size_t)m * N + n] = __floats2half2_rn(v0, v1);
                }
            }
        }
    }
}

// QKV: 2-pass, fp16 out (q scaled by 1/8)
__global__ __launch_bounds__(256, 2)
void qkv16_gemm(const __half* __restrict__ Ah, const __half* __restrict__ Al,
                const __half* __restrict__ wq, const __half* __restrict__ wk,
                const __half* __restrict__ wv,
                const float* __restrict__ bq, const float* __restrict__ bk,
                const float* __restrict__ bv,
                __half* __restrict__ q16, __half* __restrict__ k16,
                __half* __restrict__ v16) {
    extern __shared__ char smem_raw[];
    const int which = blockIdx.x / 6, nb = blockIdx.x % 6;
    const __half* B = (which == 0) ? wq : (which == 1) ? wk : wv;
    const float* bias = (which == 0) ? bq : (which == 1) ? bk : bv;
    __half* Ch = (which == 0) ? q16 : (which == 1) ? k16 : v16;
    float sc = (which == 0) ? 0.125f : 1.0f;
    hgemm_core<5, 2>(Ah, Al, B, bias, sc, nullptr, Ch,
                     blockIdx.y * 128, nb * 128, DD, DD, DD, smem_u32(smem_raw));
}

// W1: 2-pass, relu + single fp16 out
__global__ __launch_bounds__(256, 2)
void ffn1_gemm(const __half* __restrict__ Ah, const __half* __restrict__ Al,
               const __half* __restrict__ Bh, const float* __restrict__ bias,
               __half* __restrict__ Ch, int N, int K) {
    extern __shared__ char smem_raw[];
    hgemm_core<6, 2>(Ah, Al, Bh, bias, 1.0f, nullptr, Ch,
                     blockIdx.y * 128, blockIdx.x * 128, N, K, K, smem_u32(smem_raw));
}

// 1-pass split-K partial GEMM (O-proj, W2)
__global__ __launch_bounds__(256, 2)
void hgemm_pk1(const __half* __restrict__ Ah, const __half* __restrict__ Bh,
               const float* __restrict__ bias, float* __restrict__ P,
               int N, int Kfull, int Ks) {
    extern __shared__ char smem_raw[];
    const int z = blockIdx.z;
    const int k0 = z * Ks;
    hgemm_core<0, 1>(Ah + k0, nullptr, Bh + k0,
                     z == 0 ? bias : nullptr, 1.0f,
                     P + (size_t)z * MTOK * N, nullptr,
                     blockIdx.y * 128, blockIdx.x * 128, N, Ks, Kfull, smem_u32(smem_raw));
}

// 1-pass LM head
__global__ __launch_bounds__(256, 2)
void lm_gemm(const __half* __restrict__ Ah, const __half* __restrict__ Bh,
             float* __restrict__ C, int N, int K) {
    extern __shared__ char smem_raw[];
    hgemm_core<0, 1>(Ah, nullptr, Bh, nullptr, 1.0f, C, nullptr,
                     blockIdx.y * 128, blockIdx.x * 128, N, K, K, smem_u32(smem_raw));
}

// ---------------- fp16 1-pass MMA flash attention ----------------------------
#define AST 144
#define ATILE (64*AST)
#define ATT_SMEM16 (ATILE + 2*2*ATILE)   /* 46080 */

__device__ __forceinline__ void att_load4(uint32_t dst, const void* src,
                                          size_t grow0, int hcol, int tid) {
    int r = tid >> 1, c0 = (tid & 1) * 4;
    const char* p = (const char*)src + ((grow0 + r) * DD + hcol + c0 * 8) * 2;
    uint32_t d = dst + r * AST + c0 * 16;
#pragma unroll
    for (int i = 0; i < 4; i++) cpasync16(d + i * 16, p + i * 16);
}

__global__ __launch_bounds__(128)
void flash_attn(const __half* __restrict__ q16,
                const __half* __restrict__ k16, const __half* __restrict__ v16,
                __half* __restrict__ c16) {
    const int qt = gridDim.x - 1 - blockIdx.x;
    const int hd = blockIdx.y, b = blockIdx.z;
    extern __shared__ char smc[];
    const uint32_t sb = smem_u32(smc);
    const uint32_t Qh_s = sb;
    const uint32_t KV = sb + ATILE;

    const int tid = threadIdx.x, wid = tid >> 5, lane = tid & 31;
    const size_t qrow0 = (size_t)(b * SS + qt * 64);
    const int hcol = hd * DK;

    att_load4(Qh_s, q16, qrow0, hcol, tid);
    {
        size_t kr = (size_t)(b * SS);
        att_load4(KV,         k16, kr, hcol, tid);
        att_load4(KV + ATILE, v16, kr, hcol, tid);
    }
    CP_COMMIT();

    float O[8][4];
    float mrow[2] = { -1e30f, -1e30f };
    float lrow[2] = { 0.f, 0.f };
#pragma unroll
    for (int nt = 0; nt < 8; nt++)
#pragma unroll
        for (int x = 0; x < 4; x++) O[nt][x] = 0.f;

    const int g = lane >> 2, t2q = (lane & 3) * 2;
    const int a_row = wid * 16 + (lane & 15);
    const uint32_t a_cs = ((lane >> 4) << 3) * 2;
    const int b_row = (lane & 7) + (((lane >> 4) & 1) << 3);
    const uint32_t b_cs = (((lane >> 3) & 1) << 3) * 2;
    const int v_row = (lane & 15);
    const uint32_t v_cs = ((lane >> 4) << 3) * 2;

    for (int jt = 0; jt <= qt; jt++) {
        if (jt < qt) {
            size_t kr = (size_t)(b * SS + (jt + 1) * 64);
            uint32_t nb = KV + ((jt + 1) & 1) * (2 * ATILE);
            att_load4(nb,         k16, kr, hcol, tid);
            att_load4(nb + ATILE, v16, kr, hcol, tid);
            CP_COMMIT();
            CP_WAIT(1);
        } else {
            CP_WAIT(0);
        }
        __syncthreads();

        const uint32_t Kh_s = KV + (jt & 1) * (2 * ATILE);
        const uint32_t Vh_s = Kh_s + ATILE;

        float S[8][4];
#pragma unroll
        for (int nt = 0; nt < 8; nt++)
#pragma unroll
            for (int x = 0; x < 4; x++) S[nt][x] = 0.f;

#pragma unroll
        for (int ks = 0; ks < 4; ks++) {
            uint32_t Qf[4];
            ldsm4(Qf, Qh_s + a_row * AST + ks * 32 + a_cs);
#pragma unroll
            for (int p = 0; p < 4; p++) {
                uint32_t Kf[4];
                ldsm4(Kf, Kh_s + (p * 16 + b_row) * AST + ks * 32 + b_cs);
#pragma unroll
                for (int q = 0; q < 2; q++)
                    mma16816h(S[p * 2 + q], Qf, &Kf[q * 2]);
            }
        }

        const bool diag = (jt == qt);
#pragma unroll
        for (int half = 0; half < 2; half++) {
            const int rloc = wid * 16 + g + half * 8;
            float mt = -1e30f;
#pragma unroll
            for (int nt = 0; nt < 8; nt++) {
                float s0 = S[nt][half * 2], s1 = S[nt][half * 2 + 1];
                if (diag) {
                    if (nt * 8 + t2q > rloc)     s0 = -1e30f;
                    if (nt * 8 + t2q + 1 > rloc) s1 = -1e30f;
                }
                S[nt][half * 2] = s0; S[nt][half * 2 + 1] = s1;
                mt = fmaxf(mt, fmaxf(s0, s1));
            }
            mt = fmaxf(mt, __shfl_xor_sync(0xffffffffu, mt, 1));
            mt = fmaxf(mt, __shfl_xor_sync(0xffffffffu, mt, 2));
            float mn = fmaxf(mrow[half], mt);
            float f = __expf(mrow[half] - mn);
            mrow[half] = mn;
            float rs = 0.f;
#pragma unroll
            for (int nt = 0; nt < 8; nt++) {
                float e0 = __expf(S[nt][half * 2] - mn);
                float e1 = __expf(S[nt][half * 2 + 1] - mn);
                S[nt][half * 2] = e0; S[nt][half * 2 + 1] = e1;
                rs += e0 + e1;
            }
            rs += __shfl_xor_sync(0xffffffffu, rs, 1);
            rs += __shfl_xor_sync(0xffffffffu, rs, 2);
            lrow[half] = lrow[half] * f + rs;
#pragma unroll
            for (int nt = 0; nt < 8; nt++) {
                O[nt][half * 2] *= f; O[nt][half * 2 + 1] *= f;
            }
        }

        // O += P @ V (1-pass: P single-rounded to fp16)
#pragma unroll
        for (int ks = 0; ks < 4; ks++) {
            uint32_t Ph[4];
#pragma unroll
            for (int q4 = 0; q4 < 4; q4++) {
                int tile = 2 * ks + (q4 >> 1);
                int o = (q4 & 1) * 2;
                __half2 hh = __floats2half2_rn(S[tile][o], S[tile][o + 1]);
                Ph[q4] = *(uint32_t*)&hh;
            }
#pragma unroll
            for (int nt = 0; nt < 4; nt++) {
                uint32_t Vf[4];
                ldsm4t(Vf, Vh_s + (ks * 16 + v_row) * AST + nt * 32 + v_cs);
#pragma unroll
                for (int q = 0; q < 2; q++)
                    mma16816h(O[nt * 2 + q], Ph, &Vf[q * 2]);
            }
        }
        __syncthreads();
    }

    float inv[2] = { 1.0f / lrow[0], 1.0f / lrow[1] };
#pragma unroll
    for (int nt = 0; nt < 8; nt++) {
#pragma unroll
        for (int half = 0; half < 2; half++) {
            size_t row = qrow0 + wid * 16 + g + half * 8;
            int col = hcol + nt * 8 + t2q;
            *(__half2*)&c16[row * DD + col] =
                __floats2half2_rn(O[nt][half * 2] * inv[half],
                                  O[nt][half * 2 + 1] * inv[half]);
        }
    }
}

// ---------------- driver -----------------------------------------------------
extern "C" void kernel_launch(void* const* d_in, const int* in_sizes, int n_in,
                              void* d_out, int out_size) {
    (void)in_sizes; (void)n_in; (void)out_size;
    const float* tok  = (const float*)d_in[1];
    const float* pos  = (const float*)d_in[2];
    const float* bq   = (const float*)d_in[4];
    const float* bk   = (const float*)d_in[6];
    const float* bv   = (const float*)d_in[8];
    const float* bo   = (const float*)d_in[10];
    const float* b1   = (const float*)d_in[12];
    const float* b2   = (const float*)d_in[14];
    const float* ln1g = (const float*)d_in[15];
    const float* ln1b = (const float*)d_in[16];
    const float* ln2g = (const float*)d_in[17];
    const float* ln2b = (const float*)d_in[18];
    const float* lnfg = (const float*)d_in[19];
    const float* lnfb = (const float*)d_in[20];
    float* out = (float*)d_out;

    float *h, *pp;
    cudaGetSymbolAddress((void**)&h,  g_h);
    cudaGetSymbolAddress((void**)&pp, g_p);

    __half *t16, *e16h, *e16l, *w16q, *w16k, *w16v, *w16o, *w16f1, *w16f2;
    __half *q16, *k16, *v16, *a16, *f16;
    cudaGetSymbolAddress((void**)&t16,   g_t16);
    cudaGetSymbolAddress((void**)&e16h,  g_e16h);
    cudaGetSymbolAddress((void**)&e16l,  g_e16l);
    cudaGetSymbolAddress((void**)&w16q,  g_w16q);
    cudaGetSymbolAddress((void**)&w16k,  g_w16k);
    cudaGetSymbolAddress((void**)&w16v,  g_w16v);
    cudaGetSymbolAddress((void**)&w16o,  g_w16o);
    cudaGetSymbolAddress((void**)&w16f1, g_w16f1);
    cudaGetSymbolAddress((void**)&w16f2, g_w16f2);
    cudaGetSymbolAddress((void**)&q16,   g_q16);
    cudaGetSymbolAddress((void**)&k16,   g_k16);
    cudaGetSymbolAddress((void**)&v16,   g_v16);
    cudaGetSymbolAddress((void**)&a16,   g_a16);
    cudaGetSymbolAddress((void**)&f16,   g_f16);

    cudaFuncSetAttribute(qkv16_gemm, cudaFuncAttributeMaxDynamicSharedMemorySize, GSMEM_H);
    cudaFuncSetAttribute(ffn1_gemm,  cudaFuncAttributeMaxDynamicSharedMemorySize, GSMEM_H);
    cudaFuncSetAttribute(hgemm_pk1,  cudaFuncAttributeMaxDynamicSharedMemorySize, GSMEM_L1);
    cudaFuncSetAttribute(lm_gemm,    cudaFuncAttributeMaxDynamicSharedMemorySize, GSMEM_L1);
    cudaFuncSetAttribute(flash_attn, cudaFuncAttributeMaxDynamicSharedMemorySize, ATT_SMEM16);

    // launch 0: embed
    embedcvt_kernel<<<(MTOK * DD + 255) / 256, 256>>>((const long long*)d_in[0], tok, pos);
    // launch 1: all six layer weight tensors -> fp16
    {
        const int nD4 = LL * DD * DD / 4;
        const int nF4 = LL * FF * DD / 4;
        dim3 gw((nF4 + 255) / 256, 6);
        cvtw6_kernel<<<gw, 256>>>(
            (const float4*)d_in[3],  (__half2*)w16q,  nD4,
            (const float4*)d_in[5],  (__half2*)w16k,  nD4,
            (const float4*)d_in[7],  (__half2*)w16v,  nD4,
            (const float4*)d_in[9],  (__half2*)w16o,  nD4,
            (const float4*)d_in[11], (__half2*)w16f1, nF4,
            (const float4*)d_in[13], (__half2*)w16f2, nF4);
    }

    dim3 gQKV(18, MTOK / 128);           // (18, 16)
    dim3 gPK(DD / 128, MTOK / 128, 3);   // (6, 16, 3)
    dim3 gF(FF / 128, MTOK / 128);       // (24, 16)
    dim3 gV(VV / 128, MTOK / 128);       // (250, 16)
    dim3 gA(SS / 64, HH, BB);            // (16, 12, 2)
    const int gLN = MTOK / 8;

    for (int l = 0; l < LL; l++) {
        const size_t wD = (size_t)l * DD * DD;
        if (l == 0)
            ln16_kernel<<<gLN, 256>>>(h, ln1g, ln1b, e16h, e16l);          // launch 2
        else
            ln_res16_kernel<<<gLN, 256>>>(h, pp, ln1g + l * DD, ln1b + l * DD, e16h, e16l);
        qkv16_gemm<<<gQKV, 256, GSMEM_H>>>(e16h, e16l,                     // launch 3 (l=0) — profiled
                                           w16q + wD, w16k + wD, w16v + wD,
                                           bq + l * DD, bk + l * DD, bv + l * DD,
                                           q16, k16, v16);
        flash_attn<<<gA, 128, ATT_SMEM16>>>(q16, k16, v16, a16);
        hgemm_pk1<<<gPK, 256, GSMEM_L1>>>(a16, w16o + wD, bo + l * DD,
                                          pp, DD, DD, DD / 3);
        ln_res16_kernel<<<gLN, 256>>>(h, pp, ln2g + l * DD, ln2b + l * DD, e16h, e16l);
        ffn1_gemm<<<gF, 256, GSMEM_H>>>(e16h, e16l, w16f1 + (size_t)l * FF * DD,
                                        b1 + l * FF, f16, FF, DD);
        hgemm_pk1<<<gPK, 256, GSMEM_L1>>>(f16, w16f2 + (size_t)l * DD * FF,
                                          b2 + l * DD, pp, DD, FF, FF / 3);
    }

    // LM head (1-pass fp16)
    {
        int n4 = VV * DD / 4;
        cvt16_kernel<<<(n4 + 255) / 256, 256>>>((const float4*)tok, (__half2*)t16, n4);
    }
    ln_res16_kernel<<<gLN, 256>>>(h, pp, lnfg, lnfb, e16h, e16l);
    lm_gemm<<<gV, 256, GSMEM_L1>>>(e16h, t16, out, VV, DD);
}